// round 14
// baseline (speedup 1.0000x reference)
#include <cuda_runtime.h>
#include <cuda_fp16.h>
#include <cstdint>

// ---------------------------------------------------------------------------
// Problem constants
// ---------------------------------------------------------------------------
#define BATCH 16
#define CIN   512
#define CMID  256
#define HOUT  64
#define WOUT  64
#define NOUT  (BATCH * CMID * HOUT * WOUT)   // 16,777,216

// ---------------------------------------------------------------------------
// Device-global scratch (no allocations allowed)
// ---------------------------------------------------------------------------
__device__ __half g_Y1[NOUT];                // branch-1 interleaved output (pre-BN, fp16)
__device__ __half g_Y2[NOUT];                // branch-2 interleaved output (fp16)
__device__ __half g_O1[NOUT];                // conv9 output (pre-BN, fp16)
__device__ float g_a1[CMID], g_s1[CMID];
__device__ float g_a2[CMID], g_s2[CMID];
__device__ float g_a3[CMID], g_s3[CMID];
__device__ float g_biasAll[2048];

// Deterministic BN partials: [slot][ch] (sum, sumsq) — fp32, from registers
__device__ float2 g_part1[2048 * 128];       // phase-1 CTAs (2 MB)
__device__ float2 g_part2[1024 * 128];       // phase-2 CTAs (1 MB)

// Padded, channel-innermost activations (fp16)
__device__ __half g_Xp [BATCH * 34 * 34 * CIN];
__device__ __half g_X2p[BATCH * 66 * 66 * CMID];

// Tap-major weights (fp16, zero-padded to 3x3): [tap][M][Cin]
__device__ __half g_Wb[9 * 2048 * CIN];
__device__ __half g_W9[9 * 256 * CMID];

// ---------------------------------------------------------------------------
// Helpers (base sm_80+ features only — valid on plain sm_103 target)
// ---------------------------------------------------------------------------
__device__ __forceinline__ uint32_t smem_u32(const void* p) {
    uint32_t a;
    asm("{ .reg .u64 t; cvta.to.shared.u64 t, %1; cvt.u32.u64 %0, t; }" : "=r"(a) : "l"(p));
    return a;
}
__device__ __forceinline__ uint32_t sw128(uint32_t off) { return off ^ ((off >> 3) & 0x70); }

#define CP16(saddr, gptr) \
    asm volatile("cp.async.cg.shared.global [%0], [%1], 16;" :: "r"(saddr), "l"(gptr))
#define CP_COMMIT() asm volatile("cp.async.commit_group;" ::: "memory")
#define CP_WAIT1()  asm volatile("cp.async.wait_group 1;" ::: "memory")

#define LDSM4(r0, r1, r2, r3, addr) \
    asm volatile("ldmatrix.sync.aligned.m8n8.x4.shared.b16 {%0,%1,%2,%3}, [%4];" \
                 : "=r"(r0), "=r"(r1), "=r"(r2), "=r"(r3) : "r"(addr))

#define MMA_F16(d, a, b) \
    asm volatile("mma.sync.aligned.m16n8k16.row.col.f32.f16.f16.f32 " \
                 "{%0,%1,%2,%3}, {%4,%5,%6,%7}, {%8,%9}, {%0,%1,%2,%3};" \
                 : "+f"((d)[0]), "+f"((d)[1]), "+f"((d)[2]), "+f"((d)[3]) \
                 : "r"((a)[0]), "r"((a)[1]), "r"((a)[2]), "r"((a)[3]),   \
                   "r"((b)[0]), "r"((b)[1]))

// ---------------------------------------------------------------------------
// Pre-pass: pad + transpose to channel-innermost + fp16 convert.
// ---------------------------------------------------------------------------
template <int C, int H, bool AFFINE>
__global__ void pad_transpose_kernel(const float* __restrict__ src_arg)
{
    constexpr int HP = H + 2, WP = H + 2;
    constexpr int CB = C / 64;
    __shared__ float sm[64][H + 1];

    const int bid = blockIdx.x;
    const int cb  = bid % CB;
    const int y   = (bid / CB) % HP;
    const int img = bid / (CB * HP);
    const int tid = threadIdx.x;

    __half* oh = (AFFINE ? g_X2p : g_Xp) + ((size_t)(img * HP + y)) * WP * C + cb * 64;

    if (y == 0 || y == HP - 1) {
        for (int t = tid; t < WP * 64; t += 256) {
            int x = t >> 6, ci = t & 63;
            oh[(size_t)x * C + ci] = __float2half_rn(0.0f);
        }
        return;
    }

    for (int t = tid; t < 64 * H; t += 256) {
        int ci = t / H, x = t % H;
        int ch = cb * 64 + ci;
        float v;
        if (AFFINE) {
            const float yv = __half2float(g_Y1[((size_t)(img * C + ch) * H + (y - 1)) * H + x]);
            v = fmaxf(0.0f, fmaf(yv, g_a1[ch], g_s1[ch]));
        } else {
            v = src_arg[((size_t)(img * C + ch) * H + (y - 1)) * H + x];
        }
        sm[ci][x] = v;
    }
    __syncthreads();

    for (int t = tid; t < WP * 64; t += 256) {
        int x = t >> 6, ci = t & 63;
        float v = (x >= 1 && x <= H) ? sm[ci][x - 1] : 0.0f;
        oh[(size_t)x * C + ci] = __float2half_rn(v);
    }
}

// ---------------------------------------------------------------------------
// Pre-pass: all conv weights -> tap-major zero-padded 3x3 fp16 + bias table.
// ---------------------------------------------------------------------------
__global__ void prep_weights_kernel(
    const float* __restrict__ w0, const float* __restrict__ w1,
    const float* __restrict__ w2, const float* __restrict__ w3,
    const float* __restrict__ w4, const float* __restrict__ w5,
    const float* __restrict__ w6, const float* __restrict__ w7,
    const float* __restrict__ b0, const float* __restrict__ b1,
    const float* __restrict__ b2, const float* __restrict__ b3,
    const float* __restrict__ b4, const float* __restrict__ b5,
    const float* __restrict__ b6, const float* __restrict__ b7,
    const float* __restrict__ w9)
{
    const int idx = blockIdx.x * 256 + threadIdx.x;
    const float* W[8] = {w0, w1, w2, w3, w4, w5, w6, w7};
    const float* B[8] = {b0, b1, b2, b3, b4, b5, b6, b7};
    const int KH[8] = {3, 2, 3, 2, 3, 2, 3, 2};
    const int KW[8] = {3, 3, 2, 2, 3, 3, 2, 2};

    if (idx < 2048) g_biasAll[idx] = B[idx >> 8][idx & 255];

    if (idx < 9 * 2048 * 512) {
        const int ci  = idx & 511;
        const int m   = (idx >> 9) & 2047;
        const int tap = idx >> 20;
        const int conv = m >> 8, co = m & 255;
        const int kh = tap / 3, kw = tap % 3;
        float v = 0.0f;
        if (kh < KH[conv] && kw < KW[conv])
            v = W[conv][((size_t)(co * CIN + ci) * KH[conv] + kh) * KW[conv] + kw];
        g_Wb[idx] = __float2half_rn(v);
        return;
    }
    const int j = idx - 9 * 2048 * 512;      // conv9 block: 9*256*256
    if (j >= 9 * 256 * 256) return;
    const int ci = j & 255;
    const int co = (j >> 8) & 255;
    const int tap = j >> 16;
    const int kh = tap / 3, kw = tap % 3;
    float v = w9[((size_t)(co * CMID + ci) * 3 + kh) * 3 + kw];
    g_W9[j] = __float2half_rn(v);
}

// ---------------------------------------------------------------------------
// mma.sync implicit-conv GEMM, fp16 x fp16 -> fp32.
// CTA tile 128(M) x 128(N px), 128 THREADS / 4 warps, warp tile 64x64
// (4 m16 x 8 n8) — halves smem-crossbar read traffic per MMA vs 64x32.
// K chunked by 64 channels at a fixed live tap, cp.async 3-stage pipeline,
// 2 CTAs/SM (128 threads x ~200 regs fits the 256-reg budget).
// Epilogue: fp16 interleaved scatter + deterministic fp32 BN partials.
// ---------------------------------------------------------------------------
template <int KH, int KW, int CIN_T, int WDIM, int ROWS, int MTOT, bool PHASE2>
__device__ __forceinline__ void run_gemm(
    char* smem_c, uint32_t sb, int tid, int wid, int lane,
    int m0, int img, int i0, const float* __restrict__ bias9)
{
    constexpr int HP = WDIM + 2, WP = WDIM + 2;
    constexpr int KCH = CIN_T / 64;
    constexpr int NCHUNK = KH * KW * KCH;
    constexpr int CI_SHIFT = (WDIM == 32) ? 5 : 6;
    constexpr uint32_t BUF = 32768;

    const float4* A4 = reinterpret_cast<const float4*>(PHASE2 ? g_W9 : g_Wb);
    const float4* B4 = reinterpret_cast<const float4*>(PHASE2 ? g_X2p : g_Xp);

    // ---- staging: 16 cp.async x 16B per thread per chunk (128 threads) ----
    auto stage = [&](int chunk, int buf) {
        const int tap_id = chunk / KCH;
        const int ci0 = (chunk - tap_id * KCH) * 64;
        const int kh = tap_id / KW, kw = tap_id - (tap_id / KW) * KW;
        const int tapA = kh * 3 + kw;                 // storage tap index (3x3 grid)
        const uint32_t bb = sb + buf * BUF;
#pragma unroll
        for (int it = 0; it < 8; ++it) {
            const int t = tid + it * 128;
            const int row = t >> 3, g = t & 7;
            const uint32_t off = sw128(row * 128 + g * 16);
            const long srcA = ((((long)(tapA * MTOT + m0 + row) * CIN_T + ci0)) >> 3) + g;
            CP16(bb + off, A4 + srcA);
            const int r = row >> CI_SHIFT, j = row & (WDIM - 1);
            const int y = i0 + r + kh, x = j + kw;
            const long srcB = ((((long)((img * HP + y) * WP + x) * CIN_T + ci0)) >> 3) + g;
            CP16(bb + 16384 + off, B4 + srcB);
        }
    };

    // ---- per-lane ldmatrix addressing components ----
    const int sub = lane >> 3, r8 = lane & 7;
    const int wm = wid & 1, wn = wid >> 1;              // 2x2 warp grid
    const int arow_b = wm * 64 + ((sub & 1) << 3) + r8; // + mt*16
    const int akoff  = (sub >> 1) << 4;
    const int brow_b = wn * 64 + ((sub >> 1) << 3) + r8;// + q*16 (q=0..3)
    const int bkoff  = (sub & 1) << 4;

    float acc[4][8][4];
#pragma unroll
    for (int a = 0; a < 4; ++a)
#pragma unroll
        for (int b = 0; b < 8; ++b)
#pragma unroll
            for (int c = 0; c < 4; ++c) acc[a][b][c] = 0.0f;

    auto compute = [&](int buf) {
        const uint32_t AB = sb + buf * BUF;
        const uint32_t BB = AB + 16384;
#pragma unroll
        for (int kk = 0; kk < 4; ++kk) {
            uint32_t af[4][4], bf[8][2];
#pragma unroll
            for (int q = 0; q < 4; ++q) {
                const uint32_t ad = BB + sw128((brow_b + q * 16) * 128 + kk * 32 + bkoff);
                LDSM4(bf[2 * q][0], bf[2 * q][1], bf[2 * q + 1][0], bf[2 * q + 1][1], ad);
            }
#pragma unroll
            for (int mt = 0; mt < 4; ++mt) {
                const uint32_t ad = AB + sw128((arow_b + mt * 16) * 128 + kk * 32 + akoff);
                LDSM4(af[mt][0], af[mt][1], af[mt][2], af[mt][3], ad);
            }
#pragma unroll
            for (int mt = 0; mt < 4; ++mt)
#pragma unroll
                for (int nt = 0; nt < 8; ++nt)
                    MMA_F16(acc[mt][nt], af[mt], bf[nt]);
        }
    };

    // ---- 3-stage pipeline, one __syncthreads per chunk ----
    stage(0, 0); CP_COMMIT();
    stage(1, 1); CP_COMMIT();
    for (int c = 0; c < NCHUNK; ++c) {
        CP_WAIT1();            // chunk c landed
        __syncthreads();       // all warps done with compute(c-1); data visible
        if (c + 2 < NCHUNK) stage(c + 2, (c + 2) % 3);
        CP_COMMIT();
        compute(c % 3);
    }

    // ---- epilogue: fp16 scatter + per-thread BN partial accumulation ----
    const float* bias = PHASE2 ? bias9 : g_biasAll;
    int qr = 0, qc = 0, coBase = m0;
    __half* Ybuf = g_O1;
    if (!PHASE2) {
        const int conv = m0 >> 8;
        const int quad = conv & 3;
        qr = quad & 1;
        qc = (quad >> 1) & 1;
        coBase = m0 & 255;
        Ybuf = (conv >= 4) ? g_Y2 : g_Y1;
    }

    float tsum[4][2], tsq[4][2];
#pragma unroll
    for (int mt = 0; mt < 4; ++mt) { tsum[mt][0] = tsum[mt][1] = tsq[mt][0] = tsq[mt][1] = 0.0f; }

#pragma unroll
    for (int mt = 0; mt < 4; ++mt) {
        const int rowA = wm * 64 + mt * 16 + (lane >> 2);
        const float bv0 = bias[m0 + rowA];
        const float bv8 = bias[m0 + rowA + 8];
        const int co0 = coBase + rowA;
#pragma unroll
        for (int nt = 0; nt < 8; ++nt) {
            const int p = wn * 64 + nt * 8 + 2 * (lane & 3);
            const float v0 = acc[mt][nt][0] + bv0;
            const float v1 = acc[mt][nt][1] + bv0;
            const float v2 = acc[mt][nt][2] + bv8;
            const float v3 = acc[mt][nt][3] + bv8;
            if (!PHASE2) {
                const int pr = p >> 5, pc = p & 31;
                const int yy = 2 * (i0 + pr) + qr;
                const int xx = 2 * pc + qc;
                __half* base0 = Ybuf + ((size_t)(img * CMID + co0) * HOUT + yy) * WOUT + xx;
                __half* base8 = base0 + (size_t)8 * HOUT * WOUT;
                base0[0] = __float2half_rn(v0);
                base0[2] = __float2half_rn(v1);
                base8[0] = __float2half_rn(v2);
                base8[2] = __float2half_rn(v3);
            } else {
                const int pr = p >> 6, pc = p & 63;
                const int yy = i0 + pr;
                __half* base0 = Ybuf + ((size_t)(img * CMID + co0) * HOUT + yy) * WOUT + pc;
                __half* base8 = base0 + (size_t)8 * HOUT * WOUT;
                *reinterpret_cast<__half2*>(base0) = __floats2half2_rn(v0, v1);
                *reinterpret_cast<__half2*>(base8) = __floats2half2_rn(v2, v3);
            }
            tsum[mt][0] += v0 + v1;           tsq[mt][0] += v0 * v0 + v1 * v1;
            tsum[mt][1] += v2 + v3;           tsq[mt][1] += v2 * v2 + v3 * v3;
        }
    }

    // ---- deterministic partial reduction: lanes -> 2 N-warps -> CTA slot ----
    __syncthreads();
    float2* part = reinterpret_cast<float2*>(smem_c);   // [wn][128 ch] = 2KB
#pragma unroll
    for (int mt = 0; mt < 4; ++mt)
#pragma unroll
        for (int c8 = 0; c8 < 2; ++c8) {
            float s = tsum[mt][c8], q = tsq[mt][c8];
            s += __shfl_xor_sync(0xffffffffu, s, 1);
            s += __shfl_xor_sync(0xffffffffu, s, 2);
            q += __shfl_xor_sync(0xffffffffu, q, 1);
            q += __shfl_xor_sync(0xffffffffu, q, 2);
            if ((lane & 3) == 0) {
                const int chl = wm * 64 + mt * 16 + (lane >> 2) + c8 * 8;
                part[wn * 128 + chl] = make_float2(s, q);
            }
        }
    __syncthreads();
    {
        const float2 p0 = part[tid], p1 = part[128 + tid];
        const float2 r = make_float2(p0.x + p1.x, p0.y + p1.y);
        const int slot = blockIdx.x * (PHASE2 ? 512 : 128) + blockIdx.y;
        (PHASE2 ? g_part2 : g_part1)[slot * 128 + tid] = r;
    }
}

// ---------------------------------------------------------------------------
// Kernel wrappers: constexpr tap dispatch per CTA (phase 1) / fixed 3x3 (phase 2)
// ---------------------------------------------------------------------------
template <int CIN_T, int WDIM, int ROWS, int MTOT, bool PHASE2>
__global__ __launch_bounds__(128, 2)
void gemm_kernel(const float* __restrict__ bias9)
{
    constexpr int NT_PER_IMG = (WDIM * WDIM) / 128;
    extern __shared__ char smem[];
    const uint32_t sb = smem_u32(smem);

    const int tid  = threadIdx.x;
    const int wid  = tid >> 5;
    const int lane = tid & 31;
    const int m0   = blockIdx.x * 128;
    const int img  = blockIdx.y / NT_PER_IMG;
    const int i0   = (blockIdx.y % NT_PER_IMG) * ROWS;

    if (PHASE2) {
        run_gemm<3, 3, CIN_T, WDIM, ROWS, MTOT, PHASE2>(smem, sb, tid, wid, lane, m0, img, i0, bias9);
    } else {
        switch ((m0 >> 8) & 3) {   // 0:(3,3) 1:(2,3) 2:(3,2) 3:(2,2)
        case 0: run_gemm<3, 3, CIN_T, WDIM, ROWS, MTOT, PHASE2>(smem, sb, tid, wid, lane, m0, img, i0, bias9); break;
        case 1: run_gemm<2, 3, CIN_T, WDIM, ROWS, MTOT, PHASE2>(smem, sb, tid, wid, lane, m0, img, i0, bias9); break;
        case 2: run_gemm<3, 2, CIN_T, WDIM, ROWS, MTOT, PHASE2>(smem, sb, tid, wid, lane, m0, img, i0, bias9); break;
        default: run_gemm<2, 2, CIN_T, WDIM, ROWS, MTOT, PHASE2>(smem, sb, tid, wid, lane, m0, img, i0, bias9); break;
        }
    }
}

// ---------------------------------------------------------------------------
// BN finalize: reduce per-CTA partials -> folded affine (a, s).
// ---------------------------------------------------------------------------
__global__ void bn_finalize12_kernel(const float* __restrict__ gA, const float* __restrict__ beA,
                                     const float* __restrict__ gB, const float* __restrict__ beB)
{
    const int which = blockIdx.y;          // 0: Y1 (convs 0-3), 1: Y2 (convs 4-7)
    const int ch = blockIdx.x;
    const int mhalf = ch >> 7, chl = ch & 127;
    const int tid = threadIdx.x;

    float s = 0.0f, q = 0.0f;
    for (int i = tid; i < 512; i += 256) {
        const int cv = i >> 7, by = i & 127;
        const int bx = (which * 4 + cv) * 2 + mhalf;
        const float2 p = g_part1[(bx * 128 + by) * 128 + chl];
        s += p.x; q += p.y;
    }
    __shared__ float rs[256], rq[256];
    rs[tid] = s; rq[tid] = q;
    __syncthreads();
    for (int off = 128; off > 0; off >>= 1) {
        if (tid < off) { rs[tid] += rs[tid + off]; rq[tid] += rq[tid + off]; }
        __syncthreads();
    }
    if (tid == 0) {
        const float inv = 1.0f / 65536.0f;
        const float mean = rs[0] * inv;
        const float var  = rq[0] * inv - mean * mean;
        const float* gamma = which ? gB : gA;
        const float* beta  = which ? beB : beA;
        const float a = gamma[ch] * rsqrtf(var + 1e-5f);
        if (which) { g_a2[ch] = a; g_s2[ch] = beta[ch] - mean * a; }
        else       { g_a1[ch] = a; g_s1[ch] = beta[ch] - mean * a; }
    }
}

__global__ void bn_finalize2_kernel(const float* __restrict__ gamma, const float* __restrict__ beta)
{
    const int ch = blockIdx.x;
    const int bx = ch >> 7, chl = ch & 127;
    const int tid = threadIdx.x;

    float s = 0.0f, q = 0.0f;
    for (int by = tid; by < 512; by += 256) {
        const float2 p = g_part2[(bx * 512 + by) * 128 + chl];
        s += p.x; q += p.y;
    }
    __shared__ float rs[256], rq[256];
    rs[tid] = s; rq[tid] = q;
    __syncthreads();
    for (int off = 128; off > 0; off >>= 1) {
        if (tid < off) { rs[tid] += rs[tid + off]; rq[tid] += rq[tid + off]; }
        __syncthreads();
    }
    if (tid == 0) {
        const float inv = 1.0f / 65536.0f;
        const float mean = rs[0] * inv;
        const float var  = rq[0] * inv - mean * mean;
        const float a = gamma[ch] * rsqrtf(var + 1e-5f);
        g_a3[ch] = a;
        g_s3[ch] = beta[ch] - mean * a;
    }
}

// ---------------------------------------------------------------------------
// Final merge: out = relu( BN2(O1) + BN12(Y2) ), 8 halves per thread.
// ---------------------------------------------------------------------------
__global__ void final_kernel(float* __restrict__ out)
{
    const int idx = blockIdx.x * blockDim.x + threadIdx.x;   // over NOUT/8
    if (idx >= NOUT / 8) return;
    const int c = (idx >> 9) & (CMID - 1);                   // 512 8-groups per plane
    const float a2 = g_a2[c], s2 = g_s2[c];
    const float a3 = g_a3[c], s3 = g_s3[c];
    const uint4 ov = reinterpret_cast<const uint4*>(g_O1)[idx];
    const uint4 yv = reinterpret_cast<const uint4*>(g_Y2)[idx];
    const uint32_t ow[4] = {ov.x, ov.y, ov.z, ov.w};
    const uint32_t yw[4] = {yv.x, yv.y, yv.z, yv.w};
    float r[8];
#pragma unroll
    for (int i = 0; i < 4; ++i) {
        const float2 o2 = __half22float2(*reinterpret_cast<const __half2*>(&ow[i]));
        const float2 y2 = __half22float2(*reinterpret_cast<const __half2*>(&yw[i]));
        r[2 * i]     = fmaxf(0.0f, fmaf(o2.x, a3, s3) + fmaf(y2.x, a2, s2));
        r[2 * i + 1] = fmaxf(0.0f, fmaf(o2.y, a3, s3) + fmaf(y2.y, a2, s2));
    }
    float4* o4 = reinterpret_cast<float4*>(out) + idx * 2;
    o4[0] = make_float4(r[0], r[1], r[2], r[3]);
    o4[1] = make_float4(r[4], r[5], r[6], r[7]);
}

// ---------------------------------------------------------------------------
// Launch sequence
// ---------------------------------------------------------------------------
extern "C" void kernel_launch(void* const* d_in, const int* in_sizes, int n_in,
                              void* d_out, int out_size)
{
    const float* x   = (const float*)d_in[0];
    const float* w1  = (const float*)d_in[1];   const float* b1  = (const float*)d_in[2];
    const float* w2  = (const float*)d_in[3];   const float* b2  = (const float*)d_in[4];
    const float* w3  = (const float*)d_in[5];   const float* b3  = (const float*)d_in[6];
    const float* w4  = (const float*)d_in[7];   const float* b4  = (const float*)d_in[8];
    const float* w5  = (const float*)d_in[9];   const float* b5  = (const float*)d_in[10];
    const float* w6  = (const float*)d_in[11];  const float* b6  = (const float*)d_in[12];
    const float* w7  = (const float*)d_in[13];  const float* b7  = (const float*)d_in[14];
    const float* w8  = (const float*)d_in[15];  const float* b8  = (const float*)d_in[16];
    const float* w9  = (const float*)d_in[17];  const float* b9  = (const float*)d_in[18];
    const float* g11 = (const float*)d_in[19];  const float* be11 = (const float*)d_in[20];
    const float* g12 = (const float*)d_in[21];  const float* be12 = (const float*)d_in[22];
    const float* g2  = (const float*)d_in[23];  const float* be2  = (const float*)d_in[24];

    const int SMEM_GEMM = 3 * 32768;   // 98,304 B (3-stage pipeline, 2 CTAs/SM)
    cudaFuncSetAttribute(gemm_kernel<512, 32, 4, 2048, false>,
                         cudaFuncAttributeMaxDynamicSharedMemorySize, SMEM_GEMM);
    cudaFuncSetAttribute(gemm_kernel<256, 64, 2, 256, true>,
                         cudaFuncAttributeMaxDynamicSharedMemorySize, SMEM_GEMM);

    // Pre-passes: all weights (incl. conv9) in one launch + input transform
    const int PREP_BLOCKS = (9 * 2048 * 512 + 9 * 256 * 256 + 255) / 256;
    prep_weights_kernel<<<PREP_BLOCKS, 256>>>(w1, w2, w3, w4, w5, w6, w7, w8,
                                              b1, b2, b3, b4, b5, b6, b7, b8, w9);
    pad_transpose_kernel<512, 32, false><<<BATCH * 34 * 8, 256>>>(x);

    // Phase-1 GEMM: all 8 unpool convs; live-tap dispatch; fp16 epilogue.
    gemm_kernel<512, 32, 4, 2048, false><<<dim3(16, 128), 128, SMEM_GEMM>>>(nullptr);

    // BN11 + BN12 finalize
    bn_finalize12_kernel<<<dim3(CMID, 2), 256>>>(g11, be11, g12, be12);

    // relu(BN11(Y1)) -> padded transposed fp16
    pad_transpose_kernel<256, 64, true><<<BATCH * 66 * 4, 256>>>(nullptr);

    // Phase-2 GEMM: conv9; fp16 epilogue.
    gemm_kernel<256, 64, 2, 256, true><<<dim3(2, 512), 128, SMEM_GEMM>>>(b9);

    // BN2 finalize
    bn_finalize2_kernel<<<CMID, 256>>>(g2, be2);

    final_kernel<<<(NOUT / 8 + 255) / 256, 256>>>((float*)d_out);
}

// round 15
// speedup vs baseline: 1.0464x; 1.0464x over previous
#include <cuda_runtime.h>
#include <cuda_fp16.h>
#include <cstdint>

// ---------------------------------------------------------------------------
// Problem constants
// ---------------------------------------------------------------------------
#define BATCH 16
#define CIN   512
#define CMID  256
#define HOUT  64
#define WOUT  64
#define NOUT  (BATCH * CMID * HOUT * WOUT)   // 16,777,216

// ---------------------------------------------------------------------------
// Device-global scratch (no allocations allowed)
// ---------------------------------------------------------------------------
__device__ __half g_Y1[NOUT];                // branch-1 interleaved output (pre-BN, fp16)
__device__ __half g_Y2[NOUT];                // branch-2 interleaved output (fp16)
__device__ __half g_O1[NOUT];                // conv9 output (pre-BN, fp16)
__device__ float g_a1[CMID], g_s1[CMID];
__device__ float g_a2[CMID], g_s2[CMID];
__device__ float g_a3[CMID], g_s3[CMID];
__device__ float g_biasAll[2048];

// Deterministic BN partials: [slot][ch] (sum, sumsq) — fp32, from registers
__device__ float2 g_part1[2048 * 128];       // phase-1 CTAs (2 MB)
__device__ float2 g_part2[1024 * 128];       // phase-2 CTAs (1 MB)

// Padded, channel-innermost activations (fp16)
__device__ __half g_Xp [BATCH * 34 * 34 * CIN];
__device__ __half g_X2p[BATCH * 66 * 66 * CMID];

// Tap-major weights (fp16, zero-padded to 3x3): [tap][M][Cin]
__device__ __half g_Wb[9 * 2048 * CIN];
__device__ __half g_W9[9 * 256 * CMID];

// LPT schedule: longest CTAs first. bx groups: convs 0,4 (72 chunks),
// then 1,5,2,6 (48), then 3,7 (32).
__device__ const int g_bxmap[16] = {0, 1, 8, 9, 2, 3, 10, 11, 4, 5, 12, 13, 6, 7, 14, 15};

// ---------------------------------------------------------------------------
// Helpers (base sm_80+ features only — valid on plain sm_103 target)
// ---------------------------------------------------------------------------
__device__ __forceinline__ uint32_t smem_u32(const void* p) {
    uint32_t a;
    asm("{ .reg .u64 t; cvta.to.shared.u64 t, %1; cvt.u32.u64 %0, t; }" : "=r"(a) : "l"(p));
    return a;
}
__device__ __forceinline__ uint32_t sw128(uint32_t off) { return off ^ ((off >> 3) & 0x70); }

#define CP16(saddr, gptr) \
    asm volatile("cp.async.cg.shared.global [%0], [%1], 16;" :: "r"(saddr), "l"(gptr))
#define CP_COMMIT() asm volatile("cp.async.commit_group;" ::: "memory")
#define CP_WAIT1()  asm volatile("cp.async.wait_group 1;" ::: "memory")

#define LDSM4(r0, r1, r2, r3, addr) \
    asm volatile("ldmatrix.sync.aligned.m8n8.x4.shared.b16 {%0,%1,%2,%3}, [%4];" \
                 : "=r"(r0), "=r"(r1), "=r"(r2), "=r"(r3) : "r"(addr))

#define MMA_F16(d, a, b) \
    asm volatile("mma.sync.aligned.m16n8k16.row.col.f32.f16.f16.f32 " \
                 "{%0,%1,%2,%3}, {%4,%5,%6,%7}, {%8,%9}, {%0,%1,%2,%3};" \
                 : "+f"((d)[0]), "+f"((d)[1]), "+f"((d)[2]), "+f"((d)[3]) \
                 : "r"((a)[0]), "r"((a)[1]), "r"((a)[2]), "r"((a)[3]),   \
                   "r"((b)[0]), "r"((b)[1]))

// ---------------------------------------------------------------------------
// Pre-pass: pad + transpose to channel-innermost + fp16 convert.
// ---------------------------------------------------------------------------
template <int C, int H, bool AFFINE>
__global__ void pad_transpose_kernel(const float* __restrict__ src_arg)
{
    constexpr int HP = H + 2, WP = H + 2;
    constexpr int CB = C / 64;
    __shared__ float sm[64][H + 1];

    const int bid = blockIdx.x;
    const int cb  = bid % CB;
    const int y   = (bid / CB) % HP;
    const int img = bid / (CB * HP);
    const int tid = threadIdx.x;

    __half* oh = (AFFINE ? g_X2p : g_Xp) + ((size_t)(img * HP + y)) * WP * C + cb * 64;

    if (y == 0 || y == HP - 1) {
        for (int t = tid; t < WP * 64; t += 256) {
            int x = t >> 6, ci = t & 63;
            oh[(size_t)x * C + ci] = __float2half_rn(0.0f);
        }
        return;
    }

    for (int t = tid; t < 64 * H; t += 256) {
        int ci = t / H, x = t % H;
        int ch = cb * 64 + ci;
        float v;
        if (AFFINE) {
            const float yv = __half2float(g_Y1[((size_t)(img * C + ch) * H + (y - 1)) * H + x]);
            v = fmaxf(0.0f, fmaf(yv, g_a1[ch], g_s1[ch]));
        } else {
            v = src_arg[((size_t)(img * C + ch) * H + (y - 1)) * H + x];
        }
        sm[ci][x] = v;
    }
    __syncthreads();

    for (int t = tid; t < WP * 64; t += 256) {
        int x = t >> 6, ci = t & 63;
        float v = (x >= 1 && x <= H) ? sm[ci][x - 1] : 0.0f;
        oh[(size_t)x * C + ci] = __float2half_rn(v);
    }
}

// ---------------------------------------------------------------------------
// Pre-pass: all conv weights -> tap-major zero-padded 3x3 fp16 + bias table.
// ---------------------------------------------------------------------------
__global__ void prep_weights_kernel(
    const float* __restrict__ w0, const float* __restrict__ w1,
    const float* __restrict__ w2, const float* __restrict__ w3,
    const float* __restrict__ w4, const float* __restrict__ w5,
    const float* __restrict__ w6, const float* __restrict__ w7,
    const float* __restrict__ b0, const float* __restrict__ b1,
    const float* __restrict__ b2, const float* __restrict__ b3,
    const float* __restrict__ b4, const float* __restrict__ b5,
    const float* __restrict__ b6, const float* __restrict__ b7,
    const float* __restrict__ w9)
{
    const int idx = blockIdx.x * 256 + threadIdx.x;
    const float* W[8] = {w0, w1, w2, w3, w4, w5, w6, w7};
    const float* B[8] = {b0, b1, b2, b3, b4, b5, b6, b7};
    const int KH[8] = {3, 2, 3, 2, 3, 2, 3, 2};
    const int KW[8] = {3, 3, 2, 2, 3, 3, 2, 2};

    if (idx < 2048) g_biasAll[idx] = B[idx >> 8][idx & 255];

    if (idx < 9 * 2048 * 512) {
        const int ci  = idx & 511;
        const int m   = (idx >> 9) & 2047;
        const int tap = idx >> 20;
        const int conv = m >> 8, co = m & 255;
        const int kh = tap / 3, kw = tap % 3;
        float v = 0.0f;
        if (kh < KH[conv] && kw < KW[conv])
            v = W[conv][((size_t)(co * CIN + ci) * KH[conv] + kh) * KW[conv] + kw];
        g_Wb[idx] = __float2half_rn(v);
        return;
    }
    const int j = idx - 9 * 2048 * 512;      // conv9 block: 9*256*256
    if (j >= 9 * 256 * 256) return;
    const int ci = j & 255;
    const int co = (j >> 8) & 255;
    const int tap = j >> 16;
    const int kh = tap / 3, kw = tap % 3;
    float v = w9[((size_t)(co * CMID + ci) * 3 + kh) * 3 + kw];
    g_W9[j] = __float2half_rn(v);
}

// ---------------------------------------------------------------------------
// mma.sync implicit-conv GEMM (R13-proven mainloop), fp16 x fp16 -> fp32.
// CTA tile 128(M) x 128(N pixels), 256 threads / 8 warps, warp tile 64x32,
// K chunked by 64 channels at a fixed live tap, cp.async 3-stage pipeline,
// 2 CTAs/SM.  Epilogue: fp16 scatter + deterministic fp32 BN partials.
// ---------------------------------------------------------------------------
template <int KH, int KW, int CIN_T, int WDIM, int ROWS, int MTOT, bool PHASE2>
__device__ __forceinline__ void run_gemm(
    char* smem_c, uint32_t sb, int tid, int wid, int lane,
    int m0, int img, int i0, int slot, const float* __restrict__ bias9)
{
    constexpr int HP = WDIM + 2, WP = WDIM + 2;
    constexpr int KCH = CIN_T / 64;
    constexpr int NCHUNK = KH * KW * KCH;
    constexpr int CI_SHIFT = (WDIM == 32) ? 5 : 6;
    constexpr uint32_t BUF = 32768;

    const float4* A4 = reinterpret_cast<const float4*>(PHASE2 ? g_W9 : g_Wb);
    const float4* B4 = reinterpret_cast<const float4*>(PHASE2 ? g_X2p : g_Xp);

    // ---- staging: 8 cp.async x 16B per thread per chunk ----
    auto stage = [&](int chunk, int buf) {
        const int tap_id = chunk / KCH;
        const int ci0 = (chunk - tap_id * KCH) * 64;
        const int kh = tap_id / KW, kw = tap_id - (tap_id / KW) * KW;
        const int tapA = kh * 3 + kw;                 // storage tap index (3x3 grid)
        const uint32_t bb = sb + buf * BUF;
#pragma unroll
        for (int it = 0; it < 4; ++it) {
            const int t = tid + it * 256;
            const int row = t >> 3, g = t & 7;
            const uint32_t off = sw128(row * 128 + g * 16);
            const long srcA = ((((long)(tapA * MTOT + m0 + row) * CIN_T + ci0)) >> 3) + g;
            CP16(bb + off, A4 + srcA);
            const int r = row >> CI_SHIFT, j = row & (WDIM - 1);
            const int y = i0 + r + kh, x = j + kw;
            const long srcB = ((((long)((img * HP + y) * WP + x) * CIN_T + ci0)) >> 3) + g;
            CP16(bb + 16384 + off, B4 + srcB);
        }
    };

    // ---- per-lane ldmatrix addressing components ----
    const int sub = lane >> 3, r8 = lane & 7;
    const int wm = wid & 1, wn = wid >> 1;
    const int arow_b = wm * 64 + ((sub & 1) << 3) + r8;   // + mt*16
    const int akoff  = (sub >> 1) << 4;
    const int brow_b = wn * 32 + ((sub >> 1) << 3) + r8;  // + q*16
    const int bkoff  = (sub & 1) << 4;

    float acc[4][4][4];
#pragma unroll
    for (int a = 0; a < 4; ++a)
#pragma unroll
        for (int b = 0; b < 4; ++b)
#pragma unroll
            for (int c = 0; c < 4; ++c) acc[a][b][c] = 0.0f;

    auto compute = [&](int buf) {
        const uint32_t AB = sb + buf * BUF;
        const uint32_t BB = AB + 16384;
#pragma unroll
        for (int kk = 0; kk < 4; ++kk) {
            uint32_t af[4][4], bf[4][2];
#pragma unroll
            for (int q = 0; q < 2; ++q) {
                const uint32_t ad = BB + sw128((brow_b + q * 16) * 128 + kk * 32 + bkoff);
                LDSM4(bf[2 * q][0], bf[2 * q][1], bf[2 * q + 1][0], bf[2 * q + 1][1], ad);
            }
#pragma unroll
            for (int mt = 0; mt < 4; ++mt) {
                const uint32_t ad = AB + sw128((arow_b + mt * 16) * 128 + kk * 32 + akoff);
                LDSM4(af[mt][0], af[mt][1], af[mt][2], af[mt][3], ad);
            }
#pragma unroll
            for (int mt = 0; mt < 4; ++mt)
#pragma unroll
                for (int nt = 0; nt < 4; ++nt)
                    MMA_F16(acc[mt][nt], af[mt], bf[nt]);
        }
    };

    // ---- 3-stage pipeline, one __syncthreads per chunk ----
    stage(0, 0); CP_COMMIT();
    stage(1, 1); CP_COMMIT();
    for (int c = 0; c < NCHUNK; ++c) {
        CP_WAIT1();            // chunk c landed
        __syncthreads();       // all warps done with compute(c-1); data visible
        if (c + 2 < NCHUNK) stage(c + 2, (c + 2) % 3);
        CP_COMMIT();
        compute(c % 3);
    }

    // ---- epilogue: fp16 scatter + per-thread BN partial accumulation ----
    const float* bias = PHASE2 ? bias9 : g_biasAll;
    int qr = 0, qc = 0, coBase = m0;
    __half* Ybuf = g_O1;
    if (!PHASE2) {
        const int conv = m0 >> 8;
        const int quad = conv & 3;
        qr = quad & 1;
        qc = (quad >> 1) & 1;
        coBase = m0 & 255;
        Ybuf = (conv >= 4) ? g_Y2 : g_Y1;
    }

    float tsum[4][2], tsq[4][2];
#pragma unroll
    for (int mt = 0; mt < 4; ++mt) { tsum[mt][0] = tsum[mt][1] = tsq[mt][0] = tsq[mt][1] = 0.0f; }

#pragma unroll
    for (int mt = 0; mt < 4; ++mt) {
        const int rowA = wm * 64 + mt * 16 + (lane >> 2);
        const float bv0 = bias[m0 + rowA];
        const float bv8 = bias[m0 + rowA + 8];
        const int co0 = coBase + rowA;
#pragma unroll
        for (int nt = 0; nt < 4; ++nt) {
            const int p = wn * 32 + nt * 8 + 2 * (lane & 3);
            const float v0 = acc[mt][nt][0] + bv0;
            const float v1 = acc[mt][nt][1] + bv0;
            const float v2 = acc[mt][nt][2] + bv8;
            const float v3 = acc[mt][nt][3] + bv8;
            if (!PHASE2) {
                const int pr = p >> 5, pc = p & 31;
                const int yy = 2 * (i0 + pr) + qr;
                const int xx = 2 * pc + qc;
                __half* base0 = Ybuf + ((size_t)(img * CMID + co0) * HOUT + yy) * WOUT + xx;
                __half* base8 = base0 + (size_t)8 * HOUT * WOUT;
                base0[0] = __float2half_rn(v0);
                base0[2] = __float2half_rn(v1);
                base8[0] = __float2half_rn(v2);
                base8[2] = __float2half_rn(v3);
            } else {
                const int pr = p >> 6, pc = p & 63;
                const int yy = i0 + pr;
                __half* base0 = Ybuf + ((size_t)(img * CMID + co0) * HOUT + yy) * WOUT + pc;
                __half* base8 = base0 + (size_t)8 * HOUT * WOUT;
                *reinterpret_cast<__half2*>(base0) = __floats2half2_rn(v0, v1);
                *reinterpret_cast<__half2*>(base8) = __floats2half2_rn(v2, v3);
            }
            tsum[mt][0] += v0 + v1;           tsq[mt][0] += v0 * v0 + v1 * v1;
            tsum[mt][1] += v2 + v3;           tsq[mt][1] += v2 * v2 + v3 * v3;
        }
    }

    // ---- deterministic partial reduction: lanes -> warps -> CTA slot ----
    __syncthreads();
    float2* part = reinterpret_cast<float2*>(smem_c);   // [wn][128 ch] = 4KB
#pragma unroll
    for (int mt = 0; mt < 4; ++mt)
#pragma unroll
        for (int c8 = 0; c8 < 2; ++c8) {
            float s = tsum[mt][c8], q = tsq[mt][c8];
            s += __shfl_xor_sync(0xffffffffu, s, 1);
            s += __shfl_xor_sync(0xffffffffu, s, 2);
            q += __shfl_xor_sync(0xffffffffu, q, 1);
            q += __shfl_xor_sync(0xffffffffu, q, 2);
            if ((lane & 3) == 0) {
                const int chl = wm * 64 + mt * 16 + (lane >> 2) + c8 * 8;
                part[wn * 128 + chl] = make_float2(s, q);
            }
        }
    __syncthreads();
    if (tid < 128) {
        const float2 p0 = part[tid], p1 = part[128 + tid], p2 = part[256 + tid], p3 = part[384 + tid];
        const float2 r = make_float2(p0.x + p1.x + p2.x + p3.x, p0.y + p1.y + p2.y + p3.y);
        (PHASE2 ? g_part2 : g_part1)[slot * 128 + tid] = r;
    }
}

// ---------------------------------------------------------------------------
// Kernel wrappers.  Phase 1: 1-D grid (2048) with LPT bx remap — longest
// CTAs (3x3 convs) launch first so the tail wave holds the shortest jobs.
// Phase 2: unchanged 2-D grid, fixed 3x3.
// ---------------------------------------------------------------------------
template <int CIN_T, int WDIM, int ROWS, int MTOT, bool PHASE2>
__global__ __launch_bounds__(256, 2)
void gemm_kernel(const float* __restrict__ bias9)
{
    constexpr int NT_PER_IMG = (WDIM * WDIM) / 128;
    extern __shared__ char smem[];
    const uint32_t sb = smem_u32(smem);

    const int tid  = threadIdx.x;
    const int wid  = tid >> 5;
    const int lane = tid & 31;

    int bx, by;
    if (PHASE2) {
        bx = blockIdx.x;
        by = blockIdx.y;
    } else {
        bx = g_bxmap[blockIdx.x >> 7];      // LPT order
        by = blockIdx.x & 127;
    }
    const int m0   = bx * 128;
    const int img  = by / NT_PER_IMG;
    const int i0   = (by % NT_PER_IMG) * ROWS;
    const int slot = bx * (PHASE2 ? 512 : 128) + by;

    if (PHASE2) {
        run_gemm<3, 3, CIN_T, WDIM, ROWS, MTOT, PHASE2>(smem, sb, tid, wid, lane, m0, img, i0, slot, bias9);
    } else {
        switch ((m0 >> 8) & 3) {   // 0:(3,3) 1:(2,3) 2:(3,2) 3:(2,2)
        case 0: run_gemm<3, 3, CIN_T, WDIM, ROWS, MTOT, PHASE2>(smem, sb, tid, wid, lane, m0, img, i0, slot, bias9); break;
        case 1: run_gemm<2, 3, CIN_T, WDIM, ROWS, MTOT, PHASE2>(smem, sb, tid, wid, lane, m0, img, i0, slot, bias9); break;
        case 2: run_gemm<3, 2, CIN_T, WDIM, ROWS, MTOT, PHASE2>(smem, sb, tid, wid, lane, m0, img, i0, slot, bias9); break;
        default: run_gemm<2, 2, CIN_T, WDIM, ROWS, MTOT, PHASE2>(smem, sb, tid, wid, lane, m0, img, i0, slot, bias9); break;
        }
    }
}

// ---------------------------------------------------------------------------
// BN finalize: reduce per-CTA partials -> folded affine (a, s).
// ---------------------------------------------------------------------------
__global__ void bn_finalize12_kernel(const float* __restrict__ gA, const float* __restrict__ beA,
                                     const float* __restrict__ gB, const float* __restrict__ beB)
{
    const int which = blockIdx.y;          // 0: Y1 (convs 0-3), 1: Y2 (convs 4-7)
    const int ch = blockIdx.x;
    const int mhalf = ch >> 7, chl = ch & 127;
    const int tid = threadIdx.x;

    float s = 0.0f, q = 0.0f;
    for (int i = tid; i < 512; i += 256) {
        const int cv = i >> 7, by = i & 127;
        const int bx = (which * 4 + cv) * 2 + mhalf;
        const float2 p = g_part1[(bx * 128 + by) * 128 + chl];
        s += p.x; q += p.y;
    }
    __shared__ float rs[256], rq[256];
    rs[tid] = s; rq[tid] = q;
    __syncthreads();
    for (int off = 128; off > 0; off >>= 1) {
        if (tid < off) { rs[tid] += rs[tid + off]; rq[tid] += rq[tid + off]; }
        __syncthreads();
    }
    if (tid == 0) {
        const float inv = 1.0f / 65536.0f;
        const float mean = rs[0] * inv;
        const float var  = rq[0] * inv - mean * mean;
        const float* gamma = which ? gB : gA;
        const float* beta  = which ? beB : beA;
        const float a = gamma[ch] * rsqrtf(var + 1e-5f);
        if (which) { g_a2[ch] = a; g_s2[ch] = beta[ch] - mean * a; }
        else       { g_a1[ch] = a; g_s1[ch] = beta[ch] - mean * a; }
    }
}

__global__ void bn_finalize2_kernel(const float* __restrict__ gamma, const float* __restrict__ beta)
{
    const int ch = blockIdx.x;
    const int bx = ch >> 7, chl = ch & 127;
    const int tid = threadIdx.x;

    float s = 0.0f, q = 0.0f;
    for (int by = tid; by < 512; by += 256) {
        const float2 p = g_part2[(bx * 512 + by) * 128 + chl];
        s += p.x; q += p.y;
    }
    __shared__ float rs[256], rq[256];
    rs[tid] = s; rq[tid] = q;
    __syncthreads();
    for (int off = 128; off > 0; off >>= 1) {
        if (tid < off) { rs[tid] += rs[tid + off]; rq[tid] += rq[tid + off]; }
        __syncthreads();
    }
    if (tid == 0) {
        const float inv = 1.0f / 65536.0f;
        const float mean = rs[0] * inv;
        const float var  = rq[0] * inv - mean * mean;
        const float a = gamma[ch] * rsqrtf(var + 1e-5f);
        g_a3[ch] = a;
        g_s3[ch] = beta[ch] - mean * a;
    }
}

// ---------------------------------------------------------------------------
// Final merge: out = relu( BN2(O1) + BN12(Y2) ), 8 halves per thread.
// ---------------------------------------------------------------------------
__global__ void final_kernel(float* __restrict__ out)
{
    const int idx = blockIdx.x * blockDim.x + threadIdx.x;   // over NOUT/8
    if (idx >= NOUT / 8) return;
    const int c = (idx >> 9) & (CMID - 1);                   // 512 8-groups per plane
    const float a2 = g_a2[c], s2 = g_s2[c];
    const float a3 = g_a3[c], s3 = g_s3[c];
    const uint4 ov = reinterpret_cast<const uint4*>(g_O1)[idx];
    const uint4 yv = reinterpret_cast<const uint4*>(g_Y2)[idx];
    const uint32_t ow[4] = {ov.x, ov.y, ov.z, ov.w};
    const uint32_t yw[4] = {yv.x, yv.y, yv.z, yv.w};
    float r[8];
#pragma unroll
    for (int i = 0; i < 4; ++i) {
        const float2 o2 = __half22float2(*reinterpret_cast<const __half2*>(&ow[i]));
        const float2 y2 = __half22float2(*reinterpret_cast<const __half2*>(&yw[i]));
        r[2 * i]     = fmaxf(0.0f, fmaf(o2.x, a3, s3) + fmaf(y2.x, a2, s2));
        r[2 * i + 1] = fmaxf(0.0f, fmaf(o2.y, a3, s3) + fmaf(y2.y, a2, s2));
    }
    float4* o4 = reinterpret_cast<float4*>(out) + idx * 2;
    o4[0] = make_float4(r[0], r[1], r[2], r[3]);
    o4[1] = make_float4(r[4], r[5], r[6], r[7]);
}

// ---------------------------------------------------------------------------
// Launch sequence
// ---------------------------------------------------------------------------
extern "C" void kernel_launch(void* const* d_in, const int* in_sizes, int n_in,
                              void* d_out, int out_size)
{
    const float* x   = (const float*)d_in[0];
    const float* w1  = (const float*)d_in[1];   const float* b1  = (const float*)d_in[2];
    const float* w2  = (const float*)d_in[3];   const float* b2  = (const float*)d_in[4];
    const float* w3  = (const float*)d_in[5];   const float* b3  = (const float*)d_in[6];
    const float* w4  = (const float*)d_in[7];   const float* b4  = (const float*)d_in[8];
    const float* w5  = (const float*)d_in[9];   const float* b5  = (const float*)d_in[10];
    const float* w6  = (const float*)d_in[11];  const float* b6  = (const float*)d_in[12];
    const float* w7  = (const float*)d_in[13];  const float* b7  = (const float*)d_in[14];
    const float* w8  = (const float*)d_in[15];  const float* b8  = (const float*)d_in[16];
    const float* w9  = (const float*)d_in[17];  const float* b9  = (const float*)d_in[18];
    const float* g11 = (const float*)d_in[19];  const float* be11 = (const float*)d_in[20];
    const float* g12 = (const float*)d_in[21];  const float* be12 = (const float*)d_in[22];
    const float* g2  = (const float*)d_in[23];  const float* be2  = (const float*)d_in[24];

    const int SMEM_GEMM = 3 * 32768;   // 98,304 B (3-stage pipeline, 2 CTAs/SM)
    cudaFuncSetAttribute(gemm_kernel<512, 32, 4, 2048, false>,
                         cudaFuncAttributeMaxDynamicSharedMemorySize, SMEM_GEMM);
    cudaFuncSetAttribute(gemm_kernel<256, 64, 2, 256, true>,
                         cudaFuncAttributeMaxDynamicSharedMemorySize, SMEM_GEMM);

    // Pre-passes: all weights (incl. conv9) in one launch + input transform
    const int PREP_BLOCKS = (9 * 2048 * 512 + 9 * 256 * 256 + 255) / 256;
    prep_weights_kernel<<<PREP_BLOCKS, 256>>>(w1, w2, w3, w4, w5, w6, w7, w8,
                                              b1, b2, b3, b4, b5, b6, b7, b8, w9);
    pad_transpose_kernel<512, 32, false><<<BATCH * 34 * 8, 256>>>(x);

    // Phase-1 GEMM: 1-D LPT-ordered grid; live-tap dispatch; fp16 epilogue.
    gemm_kernel<512, 32, 4, 2048, false><<<2048, 256, SMEM_GEMM>>>(nullptr);

    // BN11 + BN12 finalize
    bn_finalize12_kernel<<<dim3(CMID, 2), 256>>>(g11, be11, g12, be12);

    // relu(BN11(Y1)) -> padded transposed fp16
    pad_transpose_kernel<256, 64, true><<<BATCH * 66 * 4, 256>>>(nullptr);

    // Phase-2 GEMM: conv9; fp16 epilogue.
    gemm_kernel<256, 64, 2, 256, true><<<dim3(2, 512), 256, SMEM_GEMM>>>(b9);

    // BN2 finalize
    bn_finalize2_kernel<<<CMID, 256>>>(g2, be2);

    final_kernel<<<(NOUT / 8 + 255) / 256, 256>>>((float*)d_out);
}

// round 16
// speedup vs baseline: 1.2882x; 1.2311x over previous
#include <cuda_runtime.h>
#include <cuda_fp16.h>
#include <cstdint>

// ---------------------------------------------------------------------------
// Problem constants
// ---------------------------------------------------------------------------
#define BATCH 16
#define CIN   512
#define CMID  256
#define HOUT  64
#define WOUT  64
#define NOUT  (BATCH * CMID * HOUT * WOUT)   // 16,777,216

// ---------------------------------------------------------------------------
// Device-global scratch (no allocations allowed)
// ---------------------------------------------------------------------------
__device__ __half g_Y1[NOUT];                // branch-1 interleaved output (pre-BN, fp16)
__device__ __half g_Y2[NOUT];                // branch-2 interleaved output (fp16)
__device__ __half g_O1[NOUT];                // conv9 output (pre-BN, fp16)
__device__ float g_a1[CMID], g_s1[CMID];
__device__ float g_a2[CMID], g_s2[CMID];
__device__ float g_a3[CMID], g_s3[CMID];
__device__ float g_biasAll[2048];

// Deterministic BN partials: [slot][ch] (sum, sumsq) — fp32, from registers
__device__ float2 g_part1[2048 * 128];       // phase-1 CTAs (2 MB)
__device__ float2 g_part2[1024 * 128];       // phase-2 CTAs (1 MB)

// Padded, channel-innermost activations (fp16)
__device__ __half g_Xp [BATCH * 34 * 34 * CIN];
__device__ __half g_X2p[BATCH * 66 * 66 * CMID];

// Tap-major weights (fp16): [tap][M][Cin].  Only LIVE taps are written/read.
__device__ __half g_Wb[9 * 2048 * CIN];
__device__ __half g_W9[9 * 256 * CMID];

// LPT schedule: longest CTAs first. bx groups: convs 0,4 (72 chunks),
// then 1,5,2,6 (48), then 3,7 (32).
__device__ const int g_bxmap[16] = {0, 1, 8, 9, 2, 3, 10, 11, 4, 5, 12, 13, 6, 7, 14, 15};

// ---------------------------------------------------------------------------
// Helpers (base sm_80+ features only — valid on plain sm_103 target)
// ---------------------------------------------------------------------------
__device__ __forceinline__ uint32_t smem_u32(const void* p) {
    uint32_t a;
    asm("{ .reg .u64 t; cvta.to.shared.u64 t, %1; cvt.u32.u64 %0, t; }" : "=r"(a) : "l"(p));
    return a;
}
__device__ __forceinline__ uint32_t sw128(uint32_t off) { return off ^ ((off >> 3) & 0x70); }

#define CP16(saddr, gptr) \
    asm volatile("cp.async.cg.shared.global [%0], [%1], 16;" :: "r"(saddr), "l"(gptr))
#define CP_COMMIT() asm volatile("cp.async.commit_group;" ::: "memory")
#define CP_WAIT1()  asm volatile("cp.async.wait_group 1;" ::: "memory")

#define LDSM4(r0, r1, r2, r3, addr) \
    asm volatile("ldmatrix.sync.aligned.m8n8.x4.shared.b16 {%0,%1,%2,%3}, [%4];" \
                 : "=r"(r0), "=r"(r1), "=r"(r2), "=r"(r3) : "r"(addr))

#define MMA_F16(d, a, b) \
    asm volatile("mma.sync.aligned.m16n8k16.row.col.f32.f16.f16.f32 " \
                 "{%0,%1,%2,%3}, {%4,%5,%6,%7}, {%8,%9}, {%0,%1,%2,%3};" \
                 : "+f"((d)[0]), "+f"((d)[1]), "+f"((d)[2]), "+f"((d)[3]) \
                 : "r"((a)[0]), "r"((a)[1]), "r"((a)[2]), "r"((a)[3]),   \
                   "r"((b)[0]), "r"((b)[1]))

// ---------------------------------------------------------------------------
// Pre-pass: pad + transpose to channel-innermost + fp16 convert.
// ---------------------------------------------------------------------------
template <int C, int H, bool AFFINE>
__global__ void pad_transpose_kernel(const float* __restrict__ src_arg)
{
    constexpr int HP = H + 2, WP = H + 2;
    constexpr int CB = C / 64;
    __shared__ float sm[64][H + 1];

    const int bid = blockIdx.x;
    const int cb  = bid % CB;
    const int y   = (bid / CB) % HP;
    const int img = bid / (CB * HP);
    const int tid = threadIdx.x;

    __half* oh = (AFFINE ? g_X2p : g_Xp) + ((size_t)(img * HP + y)) * WP * C + cb * 64;

    if (y == 0 || y == HP - 1) {
        for (int t = tid; t < WP * 64; t += 256) {
            int x = t >> 6, ci = t & 63;
            oh[(size_t)x * C + ci] = __float2half_rn(0.0f);
        }
        return;
    }

    for (int t = tid; t < 64 * H; t += 256) {
        int ci = t / H, x = t % H;
        int ch = cb * 64 + ci;
        float v;
        if (AFFINE) {
            const float yv = __half2float(g_Y1[((size_t)(img * C + ch) * H + (y - 1)) * H + x]);
            v = fmaxf(0.0f, fmaf(yv, g_a1[ch], g_s1[ch]));
        } else {
            v = src_arg[((size_t)(img * C + ch) * H + (y - 1)) * H + x];
        }
        sm[ci][x] = v;
    }
    __syncthreads();

    for (int t = tid; t < WP * 64; t += 256) {
        int x = t >> 6, ci = t & 63;
        float v = (x >= 1 && x <= H) ? sm[ci][x - 1] : 0.0f;
        oh[(size_t)x * C + ci] = __float2half_rn(v);
    }
}

// ---------------------------------------------------------------------------
// Pre-pass (COALESCED): one block per (conv, co) — reads the full
// [ci][kh][kw] slab contiguously into smem, writes each LIVE tap's channel
// row as contiguous fp16.  Dead (padded) taps are never written: the GEMMs
// only stage live taps.  Blocks 0..2047: unpool convs; 2048..2303: conv9.
// ---------------------------------------------------------------------------
__global__ __launch_bounds__(128)
void prep_weights_kernel(
    const float* __restrict__ w0, const float* __restrict__ w1,
    const float* __restrict__ w2, const float* __restrict__ w3,
    const float* __restrict__ w4, const float* __restrict__ w5,
    const float* __restrict__ w6, const float* __restrict__ w7,
    const float* __restrict__ b0, const float* __restrict__ b1,
    const float* __restrict__ b2, const float* __restrict__ b3,
    const float* __restrict__ b4, const float* __restrict__ b5,
    const float* __restrict__ b6, const float* __restrict__ b7,
    const float* __restrict__ w9)
{
    __shared__ float buf[4608];              // max slab: 512*9 floats = 18.4KB
    const int bid = blockIdx.x;
    const int tid = threadIdx.x;

    if (bid < 2048) {
        const float* W[8] = {w0, w1, w2, w3, w4, w5, w6, w7};
        const float* B[8] = {b0, b1, b2, b3, b4, b5, b6, b7};
        const int KHt[8] = {3, 2, 3, 2, 3, 2, 3, 2};
        const int KWt[8] = {3, 3, 2, 2, 3, 3, 2, 2};
        const int conv = bid >> 8, co = bid & 255;
        const int KH = KHt[conv], KW = KWt[conv];
        const int n = CIN * KH * KW;

        if (tid == 0) g_biasAll[bid] = B[conv][co];

        const float* src = W[conv] + (size_t)co * n;
        for (int i = tid; i < n; i += 128) buf[i] = src[i];
        __syncthreads();

        const int m = conv * 256 + co;
        for (int kh = 0; kh < KH; ++kh)
            for (int kw = 0; kw < KW; ++kw) {
                const int tapA = kh * 3 + kw;
                __half* dst = g_Wb + ((size_t)tapA * 2048 + m) * CIN;
                for (int ci = tid; ci < CIN; ci += 128)
                    dst[ci] = __float2half_rn(buf[(ci * KH + kh) * KW + kw]);
            }
    } else {
        const int co = bid - 2048;
        const int n = CMID * 9;
        const float* src = w9 + (size_t)co * n;
        for (int i = tid; i < n; i += 128) buf[i] = src[i];
        __syncthreads();

        for (int tap = 0; tap < 9; ++tap) {
            __half* dst = g_W9 + ((size_t)tap * 256 + co) * CMID;
            for (int ci = tid; ci < CMID; ci += 128)
                dst[ci] = __float2half_rn(buf[ci * 9 + tap]);
        }
    }
}

// ---------------------------------------------------------------------------
// mma.sync implicit-conv GEMM (R13-proven mainloop), fp16 x fp16 -> fp32.
// CTA tile 128(M) x 128(N pixels), 256 threads / 8 warps, warp tile 64x32,
// K chunked by 64 channels at a fixed live tap, cp.async 3-stage pipeline,
// 2 CTAs/SM.  Epilogue: fp16 scatter + deterministic fp32 BN partials.
// ---------------------------------------------------------------------------
template <int KH, int KW, int CIN_T, int WDIM, int ROWS, int MTOT, bool PHASE2>
__device__ __forceinline__ void run_gemm(
    char* smem_c, uint32_t sb, int tid, int wid, int lane,
    int m0, int img, int i0, int slot, const float* __restrict__ bias9)
{
    constexpr int HP = WDIM + 2, WP = WDIM + 2;
    constexpr int KCH = CIN_T / 64;
    constexpr int NCHUNK = KH * KW * KCH;
    constexpr int CI_SHIFT = (WDIM == 32) ? 5 : 6;
    constexpr uint32_t BUF = 32768;

    const float4* A4 = reinterpret_cast<const float4*>(PHASE2 ? g_W9 : g_Wb);
    const float4* B4 = reinterpret_cast<const float4*>(PHASE2 ? g_X2p : g_Xp);

    // ---- staging: 8 cp.async x 16B per thread per chunk ----
    auto stage = [&](int chunk, int buf) {
        const int tap_id = chunk / KCH;
        const int ci0 = (chunk - tap_id * KCH) * 64;
        const int kh = tap_id / KW, kw = tap_id - (tap_id / KW) * KW;
        const int tapA = kh * 3 + kw;                 // storage tap index (3x3 grid)
        const uint32_t bb = sb + buf * BUF;
#pragma unroll
        for (int it = 0; it < 4; ++it) {
            const int t = tid + it * 256;
            const int row = t >> 3, g = t & 7;
            const uint32_t off = sw128(row * 128 + g * 16);
            const long srcA = ((((long)(tapA * MTOT + m0 + row) * CIN_T + ci0)) >> 3) + g;
            CP16(bb + off, A4 + srcA);
            const int r = row >> CI_SHIFT, j = row & (WDIM - 1);
            const int y = i0 + r + kh, x = j + kw;
            const long srcB = ((((long)((img * HP + y) * WP + x) * CIN_T + ci0)) >> 3) + g;
            CP16(bb + 16384 + off, B4 + srcB);
        }
    };

    // ---- per-lane ldmatrix addressing components ----
    const int sub = lane >> 3, r8 = lane & 7;
    const int wm = wid & 1, wn = wid >> 1;
    const int arow_b = wm * 64 + ((sub & 1) << 3) + r8;   // + mt*16
    const int akoff  = (sub >> 1) << 4;
    const int brow_b = wn * 32 + ((sub >> 1) << 3) + r8;  // + q*16
    const int bkoff  = (sub & 1) << 4;

    float acc[4][4][4];
#pragma unroll
    for (int a = 0; a < 4; ++a)
#pragma unroll
        for (int b = 0; b < 4; ++b)
#pragma unroll
            for (int c = 0; c < 4; ++c) acc[a][b][c] = 0.0f;

    auto compute = [&](int buf) {
        const uint32_t AB = sb + buf * BUF;
        const uint32_t BB = AB + 16384;
#pragma unroll
        for (int kk = 0; kk < 4; ++kk) {
            uint32_t af[4][4], bf[4][2];
#pragma unroll
            for (int q = 0; q < 2; ++q) {
                const uint32_t ad = BB + sw128((brow_b + q * 16) * 128 + kk * 32 + bkoff);
                LDSM4(bf[2 * q][0], bf[2 * q][1], bf[2 * q + 1][0], bf[2 * q + 1][1], ad);
            }
#pragma unroll
            for (int mt = 0; mt < 4; ++mt) {
                const uint32_t ad = AB + sw128((arow_b + mt * 16) * 128 + kk * 32 + akoff);
                LDSM4(af[mt][0], af[mt][1], af[mt][2], af[mt][3], ad);
            }
#pragma unroll
            for (int mt = 0; mt < 4; ++mt)
#pragma unroll
                for (int nt = 0; nt < 4; ++nt)
                    MMA_F16(acc[mt][nt], af[mt], bf[nt]);
        }
    };

    // ---- 3-stage pipeline, one __syncthreads per chunk ----
    stage(0, 0); CP_COMMIT();
    stage(1, 1); CP_COMMIT();
    for (int c = 0; c < NCHUNK; ++c) {
        CP_WAIT1();            // chunk c landed
        __syncthreads();       // all warps done with compute(c-1); data visible
        if (c + 2 < NCHUNK) stage(c + 2, (c + 2) % 3);
        CP_COMMIT();
        compute(c % 3);
    }

    // ---- epilogue: fp16 scatter + per-thread BN partial accumulation ----
    const float* bias = PHASE2 ? bias9 : g_biasAll;
    int qr = 0, qc = 0, coBase = m0;
    __half* Ybuf = g_O1;
    if (!PHASE2) {
        const int conv = m0 >> 8;
        const int quad = conv & 3;
        qr = quad & 1;
        qc = (quad >> 1) & 1;
        coBase = m0 & 255;
        Ybuf = (conv >= 4) ? g_Y2 : g_Y1;
    }

    float tsum[4][2], tsq[4][2];
#pragma unroll
    for (int mt = 0; mt < 4; ++mt) { tsum[mt][0] = tsum[mt][1] = tsq[mt][0] = tsq[mt][1] = 0.0f; }

#pragma unroll
    for (int mt = 0; mt < 4; ++mt) {
        const int rowA = wm * 64 + mt * 16 + (lane >> 2);
        const float bv0 = bias[m0 + rowA];
        const float bv8 = bias[m0 + rowA + 8];
        const int co0 = coBase + rowA;
#pragma unroll
        for (int nt = 0; nt < 4; ++nt) {
            const int p = wn * 32 + nt * 8 + 2 * (lane & 3);
            const float v0 = acc[mt][nt][0] + bv0;
            const float v1 = acc[mt][nt][1] + bv0;
            const float v2 = acc[mt][nt][2] + bv8;
            const float v3 = acc[mt][nt][3] + bv8;
            if (!PHASE2) {
                const int pr = p >> 5, pc = p & 31;
                const int yy = 2 * (i0 + pr) + qr;
                const int xx = 2 * pc + qc;
                __half* base0 = Ybuf + ((size_t)(img * CMID + co0) * HOUT + yy) * WOUT + xx;
                __half* base8 = base0 + (size_t)8 * HOUT * WOUT;
                base0[0] = __float2half_rn(v0);
                base0[2] = __float2half_rn(v1);
                base8[0] = __float2half_rn(v2);
                base8[2] = __float2half_rn(v3);
            } else {
                const int pr = p >> 6, pc = p & 63;
                const int yy = i0 + pr;
                __half* base0 = Ybuf + ((size_t)(img * CMID + co0) * HOUT + yy) * WOUT + pc;
                __half* base8 = base0 + (size_t)8 * HOUT * WOUT;
                *reinterpret_cast<__half2*>(base0) = __floats2half2_rn(v0, v1);
                *reinterpret_cast<__half2*>(base8) = __floats2half2_rn(v2, v3);
            }
            tsum[mt][0] += v0 + v1;           tsq[mt][0] += v0 * v0 + v1 * v1;
            tsum[mt][1] += v2 + v3;           tsq[mt][1] += v2 * v2 + v3 * v3;
        }
    }

    // ---- deterministic partial reduction: lanes -> warps -> CTA slot ----
    __syncthreads();
    float2* part = reinterpret_cast<float2*>(smem_c);   // [wn][128 ch] = 4KB
#pragma unroll
    for (int mt = 0; mt < 4; ++mt)
#pragma unroll
        for (int c8 = 0; c8 < 2; ++c8) {
            float s = tsum[mt][c8], q = tsq[mt][c8];
            s += __shfl_xor_sync(0xffffffffu, s, 1);
            s += __shfl_xor_sync(0xffffffffu, s, 2);
            q += __shfl_xor_sync(0xffffffffu, q, 1);
            q += __shfl_xor_sync(0xffffffffu, q, 2);
            if ((lane & 3) == 0) {
                const int chl = wm * 64 + mt * 16 + (lane >> 2) + c8 * 8;
                part[wn * 128 + chl] = make_float2(s, q);
            }
        }
    __syncthreads();
    if (tid < 128) {
        const float2 p0 = part[tid], p1 = part[128 + tid], p2 = part[256 + tid], p3 = part[384 + tid];
        const float2 r = make_float2(p0.x + p1.x + p2.x + p3.x, p0.y + p1.y + p2.y + p3.y);
        (PHASE2 ? g_part2 : g_part1)[slot * 128 + tid] = r;
    }
}

// ---------------------------------------------------------------------------
// Kernel wrappers.  Phase 1: 1-D grid (2048) with LPT bx remap — longest
// CTAs (3x3 convs) launch first so the tail wave holds the shortest jobs.
// Phase 2: unchanged 2-D grid, fixed 3x3.
// ---------------------------------------------------------------------------
template <int CIN_T, int WDIM, int ROWS, int MTOT, bool PHASE2>
__global__ __launch_bounds__(256, 2)
void gemm_kernel(const float* __restrict__ bias9)
{
    constexpr int NT_PER_IMG = (WDIM * WDIM) / 128;
    extern __shared__ char smem[];
    const uint32_t sb = smem_u32(smem);

    const int tid  = threadIdx.x;
    const int wid  = tid >> 5;
    const int lane = tid & 31;

    int bx, by;
    if (PHASE2) {
        bx = blockIdx.x;
        by = blockIdx.y;
    } else {
        bx = g_bxmap[blockIdx.x >> 7];      // LPT order
        by = blockIdx.x & 127;
    }
    const int m0   = bx * 128;
    const int img  = by / NT_PER_IMG;
    const int i0   = (by % NT_PER_IMG) * ROWS;
    const int slot = bx * (PHASE2 ? 512 : 128) + by;

    if (PHASE2) {
        run_gemm<3, 3, CIN_T, WDIM, ROWS, MTOT, PHASE2>(smem, sb, tid, wid, lane, m0, img, i0, slot, bias9);
    } else {
        switch ((m0 >> 8) & 3) {   // 0:(3,3) 1:(2,3) 2:(3,2) 3:(2,2)
        case 0: run_gemm<3, 3, CIN_T, WDIM, ROWS, MTOT, PHASE2>(smem, sb, tid, wid, lane, m0, img, i0, slot, bias9); break;
        case 1: run_gemm<2, 3, CIN_T, WDIM, ROWS, MTOT, PHASE2>(smem, sb, tid, wid, lane, m0, img, i0, slot, bias9); break;
        case 2: run_gemm<3, 2, CIN_T, WDIM, ROWS, MTOT, PHASE2>(smem, sb, tid, wid, lane, m0, img, i0, slot, bias9); break;
        default: run_gemm<2, 2, CIN_T, WDIM, ROWS, MTOT, PHASE2>(smem, sb, tid, wid, lane, m0, img, i0, slot, bias9); break;
        }
    }
}

// ---------------------------------------------------------------------------
// BN finalize: reduce per-CTA partials -> folded affine (a, s).
// ---------------------------------------------------------------------------
__global__ void bn_finalize12_kernel(const float* __restrict__ gA, const float* __restrict__ beA,
                                     const float* __restrict__ gB, const float* __restrict__ beB)
{
    const int which = blockIdx.y;          // 0: Y1 (convs 0-3), 1: Y2 (convs 4-7)
    const int ch = blockIdx.x;
    const int mhalf = ch >> 7, chl = ch & 127;
    const int tid = threadIdx.x;

    float s = 0.0f, q = 0.0f;
    for (int i = tid; i < 512; i += 256) {
        const int cv = i >> 7, by = i & 127;
        const int bx = (which * 4 + cv) * 2 + mhalf;
        const float2 p = g_part1[(bx * 128 + by) * 128 + chl];
        s += p.x; q += p.y;
    }
    __shared__ float rs[256], rq[256];
    rs[tid] = s; rq[tid] = q;
    __syncthreads();
    for (int off = 128; off > 0; off >>= 1) {
        if (tid < off) { rs[tid] += rs[tid + off]; rq[tid] += rq[tid + off]; }
        __syncthreads();
    }
    if (tid == 0) {
        const float inv = 1.0f / 65536.0f;
        const float mean = rs[0] * inv;
        const float var  = rq[0] * inv - mean * mean;
        const float* gamma = which ? gB : gA;
        const float* beta  = which ? beB : beA;
        const float a = gamma[ch] * rsqrtf(var + 1e-5f);
        if (which) { g_a2[ch] = a; g_s2[ch] = beta[ch] - mean * a; }
        else       { g_a1[ch] = a; g_s1[ch] = beta[ch] - mean * a; }
    }
}

__global__ void bn_finalize2_kernel(const float* __restrict__ gamma, const float* __restrict__ beta)
{
    const int ch = blockIdx.x;
    const int bx = ch >> 7, chl = ch & 127;
    const int tid = threadIdx.x;

    float s = 0.0f, q = 0.0f;
    for (int by = tid; by < 512; by += 256) {
        const float2 p = g_part2[(bx * 512 + by) * 128 + chl];
        s += p.x; q += p.y;
    }
    __shared__ float rs[256], rq[256];
    rs[tid] = s; rq[tid] = q;
    __syncthreads();
    for (int off = 128; off > 0; off >>= 1) {
        if (tid < off) { rs[tid] += rs[tid + off]; rq[tid] += rq[tid + off]; }
        __syncthreads();
    }
    if (tid == 0) {
        const float inv = 1.0f / 65536.0f;
        const float mean = rs[0] * inv;
        const float var  = rq[0] * inv - mean * mean;
        const float a = gamma[ch] * rsqrtf(var + 1e-5f);
        g_a3[ch] = a;
        g_s3[ch] = beta[ch] - mean * a;
    }
}

// ---------------------------------------------------------------------------
// Final merge: out = relu( BN2(O1) + BN12(Y2) ), 8 halves per thread.
// ---------------------------------------------------------------------------
__global__ void final_kernel(float* __restrict__ out)
{
    const int idx = blockIdx.x * blockDim.x + threadIdx.x;   // over NOUT/8
    if (idx >= NOUT / 8) return;
    const int c = (idx >> 9) & (CMID - 1);                   // 512 8-groups per plane
    const float a2 = g_a2[c], s2 = g_s2[c];
    const float a3 = g_a3[c], s3 = g_s3[c];
    const uint4 ov = reinterpret_cast<const uint4*>(g_O1)[idx];
    const uint4 yv = reinterpret_cast<const uint4*>(g_Y2)[idx];
    const uint32_t ow[4] = {ov.x, ov.y, ov.z, ov.w};
    const uint32_t yw[4] = {yv.x, yv.y, yv.z, yv.w};
    float r[8];
#pragma unroll
    for (int i = 0; i < 4; ++i) {
        const float2 o2 = __half22float2(*reinterpret_cast<const __half2*>(&ow[i]));
        const float2 y2 = __half22float2(*reinterpret_cast<const __half2*>(&yw[i]));
        r[2 * i]     = fmaxf(0.0f, fmaf(o2.x, a3, s3) + fmaf(y2.x, a2, s2));
        r[2 * i + 1] = fmaxf(0.0f, fmaf(o2.y, a3, s3) + fmaf(y2.y, a2, s2));
    }
    float4* o4 = reinterpret_cast<float4*>(out) + idx * 2;
    o4[0] = make_float4(r[0], r[1], r[2], r[3]);
    o4[1] = make_float4(r[4], r[5], r[6], r[7]);
}

// ---------------------------------------------------------------------------
// Launch sequence
// ---------------------------------------------------------------------------
extern "C" void kernel_launch(void* const* d_in, const int* in_sizes, int n_in,
                              void* d_out, int out_size)
{
    const float* x   = (const float*)d_in[0];
    const float* w1  = (const float*)d_in[1];   const float* b1  = (const float*)d_in[2];
    const float* w2  = (const float*)d_in[3];   const float* b2  = (const float*)d_in[4];
    const float* w3  = (const float*)d_in[5];   const float* b3  = (const float*)d_in[6];
    const float* w4  = (const float*)d_in[7];   const float* b4  = (const float*)d_in[8];
    const float* w5  = (const float*)d_in[9];   const float* b5  = (const float*)d_in[10];
    const float* w6  = (const float*)d_in[11];  const float* b6  = (const float*)d_in[12];
    const float* w7  = (const float*)d_in[13];  const float* b7  = (const float*)d_in[14];
    const float* w8  = (const float*)d_in[15];  const float* b8  = (const float*)d_in[16];
    const float* w9  = (const float*)d_in[17];  const float* b9  = (const float*)d_in[18];
    const float* g11 = (const float*)d_in[19];  const float* be11 = (const float*)d_in[20];
    const float* g12 = (const float*)d_in[21];  const float* be12 = (const float*)d_in[22];
    const float* g2  = (const float*)d_in[23];  const float* be2  = (const float*)d_in[24];

    const int SMEM_GEMM = 3 * 32768;   // 98,304 B (3-stage pipeline, 2 CTAs/SM)
    cudaFuncSetAttribute(gemm_kernel<512, 32, 4, 2048, false>,
                         cudaFuncAttributeMaxDynamicSharedMemorySize, SMEM_GEMM);
    cudaFuncSetAttribute(gemm_kernel<256, 64, 2, 256, true>,
                         cudaFuncAttributeMaxDynamicSharedMemorySize, SMEM_GEMM);

    // Pre-passes: coalesced weight transform (one block per output filter)
    prep_weights_kernel<<<2048 + 256, 128>>>(w1, w2, w3, w4, w5, w6, w7, w8,
                                             b1, b2, b3, b4, b5, b6, b7, b8, w9);
    pad_transpose_kernel<512, 32, false><<<BATCH * 34 * 8, 256>>>(x);

    // Phase-1 GEMM: 1-D LPT-ordered grid; live-tap dispatch; fp16 epilogue.
    gemm_kernel<512, 32, 4, 2048, false><<<2048, 256, SMEM_GEMM>>>(nullptr);

    // BN11 + BN12 finalize
    bn_finalize12_kernel<<<dim3(CMID, 2), 256>>>(g11, be11, g12, be12);

    // relu(BN11(Y1)) -> padded transposed fp16
    pad_transpose_kernel<256, 64, true><<<BATCH * 66 * 4, 256>>>(nullptr);

    // Phase-2 GEMM: conv9; fp16 epilogue.
    gemm_kernel<256, 64, 2, 256, true><<<dim3(2, 512), 256, SMEM_GEMM>>>(b9);

    // BN2 finalize
    bn_finalize2_kernel<<<CMID, 256>>>(g2, be2);

    final_kernel<<<(NOUT / 8 + 255) / 256, 256>>>((float*)d_out);
}

// round 17
// speedup vs baseline: 1.2997x; 1.0089x over previous
#include <cuda_runtime.h>
#include <cuda_fp16.h>
#include <cstdint>

// ---------------------------------------------------------------------------
// Problem constants
// ---------------------------------------------------------------------------
#define BATCH 16
#define CIN   512
#define CMID  256
#define HOUT  64
#define WOUT  64
#define NOUT  (BATCH * CMID * HOUT * WOUT)   // 16,777,216

// ---------------------------------------------------------------------------
// Device-global scratch (no allocations allowed)
// ---------------------------------------------------------------------------
__device__ __half g_Y2[NOUT];                // branch-2 interleaved output (fp16, NCHW)
__device__ __half g_O1[NOUT];                // conv9 output (pre-BN, fp16, NCHW)
__device__ float g_a1[CMID], g_s1[CMID];
__device__ float g_a2[CMID], g_s2[CMID];
__device__ float g_a3[CMID], g_s3[CMID];
__device__ float g_biasAll[2048];

// Deterministic BN partials: [slot][ch] (sum, sumsq) — fp32, from registers
__device__ float2 g_part1[2048 * 128];       // phase-1 CTAs (2 MB)
__device__ float2 g_part2[1024 * 128];       // phase-2 CTAs (1 MB)

// Padded, channel-innermost activations (fp16)
__device__ __half g_Xp [BATCH * 34 * 34 * CIN];
// X2p: branch-1 GEMM writes PRE-AFFINE values directly here (padded,
// channel-innermost); affine_x2p then applies relu(BN11) in place.
__device__ __half g_X2p[BATCH * 66 * 66 * CMID];

// Tap-major weights (fp16): [tap][M][Cin].  Only LIVE taps are written/read.
__device__ __half g_Wb[9 * 2048 * CIN];
__device__ __half g_W9[9 * 256 * CMID];

// LPT schedule: longest CTAs first. bx groups: convs 0,4 (72 chunks),
// then 1,5,2,6 (48), then 3,7 (32).
__device__ const int g_bxmap[16] = {0, 1, 8, 9, 2, 3, 10, 11, 4, 5, 12, 13, 6, 7, 14, 15};

// ---------------------------------------------------------------------------
// Helpers (base sm_80+ features only — valid on plain sm_103 target)
// ---------------------------------------------------------------------------
__device__ __forceinline__ uint32_t smem_u32(const void* p) {
    uint32_t a;
    asm("{ .reg .u64 t; cvta.to.shared.u64 t, %1; cvt.u32.u64 %0, t; }" : "=r"(a) : "l"(p));
    return a;
}
__device__ __forceinline__ uint32_t sw128(uint32_t off) { return off ^ ((off >> 3) & 0x70); }

#define CP16(saddr, gptr) \
    asm volatile("cp.async.cg.shared.global [%0], [%1], 16;" :: "r"(saddr), "l"(gptr))
#define CP_COMMIT() asm volatile("cp.async.commit_group;" ::: "memory")
#define CP_WAIT1()  asm volatile("cp.async.wait_group 1;" ::: "memory")

#define LDSM4(r0, r1, r2, r3, addr) \
    asm volatile("ldmatrix.sync.aligned.m8n8.x4.shared.b16 {%0,%1,%2,%3}, [%4];" \
                 : "=r"(r0), "=r"(r1), "=r"(r2), "=r"(r3) : "r"(addr))

#define MMA_F16(d, a, b) \
    asm volatile("mma.sync.aligned.m16n8k16.row.col.f32.f16.f16.f32 " \
                 "{%0,%1,%2,%3}, {%4,%5,%6,%7}, {%8,%9}, {%0,%1,%2,%3};" \
                 : "+f"((d)[0]), "+f"((d)[1]), "+f"((d)[2]), "+f"((d)[3]) \
                 : "r"((a)[0]), "r"((a)[1]), "r"((a)[2]), "r"((a)[3]),   \
                   "r"((b)[0]), "r"((b)[1]))

// ---------------------------------------------------------------------------
// Pre-pass: pad + transpose x (fp32 NCHW) -> g_Xp (channel-innermost fp16).
// ---------------------------------------------------------------------------
__global__ void pad_transpose_kernel(const float* __restrict__ src_arg)
{
    constexpr int C = 512, H = 32, HP = 34, WP = 34, CB = C / 64;
    __shared__ float sm[64][H + 1];

    const int bid = blockIdx.x;
    const int cb  = bid % CB;
    const int y   = (bid / CB) % HP;
    const int img = bid / (CB * HP);
    const int tid = threadIdx.x;

    __half* oh = g_Xp + ((size_t)(img * HP + y)) * WP * C + cb * 64;

    if (y == 0 || y == HP - 1) {
        for (int t = tid; t < WP * 64; t += 256) {
            int x = t >> 6, ci = t & 63;
            oh[(size_t)x * C + ci] = __float2half_rn(0.0f);
        }
        return;
    }

    for (int t = tid; t < 64 * H; t += 256) {
        int ci = t / H, x = t % H;
        int ch = cb * 64 + ci;
        sm[ci][x] = src_arg[((size_t)(img * C + ch) * H + (y - 1)) * H + x];
    }
    __syncthreads();

    for (int t = tid; t < WP * 64; t += 256) {
        int x = t >> 6, ci = t & 63;
        float v = (x >= 1 && x <= H) ? sm[ci][x - 1] : 0.0f;
        oh[(size_t)x * C + ci] = __float2half_rn(v);
    }
}

// ---------------------------------------------------------------------------
// In-place affine on X2p: border -> 0, interior -> relu(a1*v + s1).
// 8 halves (8 consecutive channels) per thread; bit-identical to the old
// pad_transpose2 path (same fp16 value, same fp32 affine, same rounding).
// ---------------------------------------------------------------------------
__global__ void affine_x2p_kernel()
{
    const int idx = blockIdx.x * blockDim.x + threadIdx.x;   // over elems/8
    constexpr int TOT8 = BATCH * 66 * 66 * CMID / 8;         // 2,230,272
    if (idx >= TOT8) return;
    const int flat = idx * 8;
    const int ch0 = flat & (CMID - 1);
    const int pos = flat >> 8;                 // (img*66 + y)*66 + x
    const int x = pos % 66;
    const int y = (pos / 66) % 66;

    uint4* p = reinterpret_cast<uint4*>(g_X2p) + idx;
    if (x == 0 || x == 65 || y == 0 || y == 65) {
        *p = make_uint4(0u, 0u, 0u, 0u);
        return;
    }
    uint4 v = *p;
    uint32_t w[4] = {v.x, v.y, v.z, v.w};
#pragma unroll
    for (int i = 0; i < 4; ++i) {
        const float2 h = __half22float2(*reinterpret_cast<const __half2*>(&w[i]));
        const float r0 = fmaxf(0.0f, fmaf(h.x, g_a1[ch0 + 2 * i],     g_s1[ch0 + 2 * i]));
        const float r1 = fmaxf(0.0f, fmaf(h.y, g_a1[ch0 + 2 * i + 1], g_s1[ch0 + 2 * i + 1]));
        *reinterpret_cast<__half2*>(&w[i]) = __floats2half2_rn(r0, r1);
    }
    *p = make_uint4(w[0], w[1], w[2], w[3]);
}

// ---------------------------------------------------------------------------
// Pre-pass (COALESCED): one block per (conv, co) — reads the full
// [ci][kh][kw] slab contiguously into smem, writes each LIVE tap's channel
// row as contiguous fp16.  Blocks 0..2047: unpool convs; 2048..2303: conv9.
// ---------------------------------------------------------------------------
__global__ __launch_bounds__(128)
void prep_weights_kernel(
    const float* __restrict__ w0, const float* __restrict__ w1,
    const float* __restrict__ w2, const float* __restrict__ w3,
    const float* __restrict__ w4, const float* __restrict__ w5,
    const float* __restrict__ w6, const float* __restrict__ w7,
    const float* __restrict__ b0, const float* __restrict__ b1,
    const float* __restrict__ b2, const float* __restrict__ b3,
    const float* __restrict__ b4, const float* __restrict__ b5,
    const float* __restrict__ b6, const float* __restrict__ b7,
    const float* __restrict__ w9)
{
    __shared__ float buf[4608];              // max slab: 512*9 floats = 18.4KB
    const int bid = blockIdx.x;
    const int tid = threadIdx.x;

    if (bid < 2048) {
        const float* W[8] = {w0, w1, w2, w3, w4, w5, w6, w7};
        const float* B[8] = {b0, b1, b2, b3, b4, b5, b6, b7};
        const int KHt[8] = {3, 2, 3, 2, 3, 2, 3, 2};
        const int KWt[8] = {3, 3, 2, 2, 3, 3, 2, 2};
        const int conv = bid >> 8, co = bid & 255;
        const int KH = KHt[conv], KW = KWt[conv];
        const int n = CIN * KH * KW;

        if (tid == 0) g_biasAll[bid] = B[conv][co];

        const float* src = W[conv] + (size_t)co * n;
        for (int i = tid; i < n; i += 128) buf[i] = src[i];
        __syncthreads();

        const int m = conv * 256 + co;
        for (int kh = 0; kh < KH; ++kh)
            for (int kw = 0; kw < KW; ++kw) {
                const int tapA = kh * 3 + kw;
                __half* dst = g_Wb + ((size_t)tapA * 2048 + m) * CIN;
                for (int ci = tid; ci < CIN; ci += 128)
                    dst[ci] = __float2half_rn(buf[(ci * KH + kh) * KW + kw]);
            }
    } else {
        const int co = bid - 2048;
        const int n = CMID * 9;
        const float* src = w9 + (size_t)co * n;
        for (int i = tid; i < n; i += 128) buf[i] = src[i];
        __syncthreads();

        for (int tap = 0; tap < 9; ++tap) {
            __half* dst = g_W9 + ((size_t)tap * 256 + co) * CMID;
            for (int ci = tid; ci < CMID; ci += 128)
                dst[ci] = __float2half_rn(buf[ci * 9 + tap]);
        }
    }
}

// ---------------------------------------------------------------------------
// mma.sync implicit-conv GEMM (R13-proven mainloop), fp16 x fp16 -> fp32.
// CTA tile 128(M) x 128(N pixels), 256 threads / 8 warps, warp tile 64x32,
// K chunked by 64 channels at a fixed live tap, cp.async 3-stage pipeline,
// 2 CTAs/SM.  Epilogue: branch-1 -> X2p (padded ch-innermost, pre-affine);
// branch-2 -> Y2 NCHW; phase-2 -> O1 NCHW; + deterministic fp32 BN partials.
// ---------------------------------------------------------------------------
template <int KH, int KW, int CIN_T, int WDIM, int ROWS, int MTOT, bool PHASE2>
__device__ __forceinline__ void run_gemm(
    char* smem_c, uint32_t sb, int tid, int wid, int lane,
    int m0, int img, int i0, int slot, const float* __restrict__ bias9)
{
    constexpr int HP = WDIM + 2, WP = WDIM + 2;
    constexpr int KCH = CIN_T / 64;
    constexpr int NCHUNK = KH * KW * KCH;
    constexpr int CI_SHIFT = (WDIM == 32) ? 5 : 6;
    constexpr uint32_t BUF = 32768;

    const float4* A4 = reinterpret_cast<const float4*>(PHASE2 ? g_W9 : g_Wb);
    const float4* B4 = reinterpret_cast<const float4*>(PHASE2 ? g_X2p : g_Xp);

    // ---- staging: 8 cp.async x 16B per thread per chunk ----
    auto stage = [&](int chunk, int buf) {
        const int tap_id = chunk / KCH;
        const int ci0 = (chunk - tap_id * KCH) * 64;
        const int kh = tap_id / KW, kw = tap_id - (tap_id / KW) * KW;
        const int tapA = kh * 3 + kw;                 // storage tap index (3x3 grid)
        const uint32_t bb = sb + buf * BUF;
#pragma unroll
        for (int it = 0; it < 4; ++it) {
            const int t = tid + it * 256;
            const int row = t >> 3, g = t & 7;
            const uint32_t off = sw128(row * 128 + g * 16);
            const long srcA = ((((long)(tapA * MTOT + m0 + row) * CIN_T + ci0)) >> 3) + g;
            CP16(bb + off, A4 + srcA);
            const int r = row >> CI_SHIFT, j = row & (WDIM - 1);
            const int y = i0 + r + kh, x = j + kw;
            const long srcB = ((((long)((img * HP + y) * WP + x) * CIN_T + ci0)) >> 3) + g;
            CP16(bb + 16384 + off, B4 + srcB);
        }
    };

    // ---- per-lane ldmatrix addressing components ----
    const int sub = lane >> 3, r8 = lane & 7;
    const int wm = wid & 1, wn = wid >> 1;
    const int arow_b = wm * 64 + ((sub & 1) << 3) + r8;   // + mt*16
    const int akoff  = (sub >> 1) << 4;
    const int brow_b = wn * 32 + ((sub >> 1) << 3) + r8;  // + q*16
    const int bkoff  = (sub & 1) << 4;

    float acc[4][4][4];
#pragma unroll
    for (int a = 0; a < 4; ++a)
#pragma unroll
        for (int b = 0; b < 4; ++b)
#pragma unroll
            for (int c = 0; c < 4; ++c) acc[a][b][c] = 0.0f;

    auto compute = [&](int buf) {
        const uint32_t AB = sb + buf * BUF;
        const uint32_t BB = AB + 16384;
#pragma unroll
        for (int kk = 0; kk < 4; ++kk) {
            uint32_t af[4][4], bf[4][2];
#pragma unroll
            for (int q = 0; q < 2; ++q) {
                const uint32_t ad = BB + sw128((brow_b + q * 16) * 128 + kk * 32 + bkoff);
                LDSM4(bf[2 * q][0], bf[2 * q][1], bf[2 * q + 1][0], bf[2 * q + 1][1], ad);
            }
#pragma unroll
            for (int mt = 0; mt < 4; ++mt) {
                const uint32_t ad = AB + sw128((arow_b + mt * 16) * 128 + kk * 32 + akoff);
                LDSM4(af[mt][0], af[mt][1], af[mt][2], af[mt][3], ad);
            }
#pragma unroll
            for (int mt = 0; mt < 4; ++mt)
#pragma unroll
                for (int nt = 0; nt < 4; ++nt)
                    MMA_F16(acc[mt][nt], af[mt], bf[nt]);
        }
    };

    // ---- 3-stage pipeline, one __syncthreads per chunk ----
    stage(0, 0); CP_COMMIT();
    stage(1, 1); CP_COMMIT();
    for (int c = 0; c < NCHUNK; ++c) {
        CP_WAIT1();            // chunk c landed
        __syncthreads();       // all warps done with compute(c-1); data visible
        if (c + 2 < NCHUNK) stage(c + 2, (c + 2) % 3);
        CP_COMMIT();
        compute(c % 3);
    }

    // ---- epilogue: scatter + per-thread BN partial accumulation ----
    const float* bias = PHASE2 ? bias9 : g_biasAll;
    int qr = 0, qc = 0, coBase = m0, conv = 0;
    if (!PHASE2) {
        conv = m0 >> 8;
        const int quad = conv & 3;
        qr = quad & 1;
        qc = (quad >> 1) & 1;
        coBase = m0 & 255;
    }
    const bool toX2p = (!PHASE2) && (conv < 4);     // branch 1 -> X2p direct

    float tsum[4][2], tsq[4][2];
#pragma unroll
    for (int mt = 0; mt < 4; ++mt) { tsum[mt][0] = tsum[mt][1] = tsq[mt][0] = tsq[mt][1] = 0.0f; }

#pragma unroll
    for (int mt = 0; mt < 4; ++mt) {
        const int rowA = wm * 64 + mt * 16 + (lane >> 2);
        const float bv0 = bias[m0 + rowA];
        const float bv8 = bias[m0 + rowA + 8];
        const int co0 = coBase + rowA;
#pragma unroll
        for (int nt = 0; nt < 4; ++nt) {
            const int p = wn * 32 + nt * 8 + 2 * (lane & 3);
            const float v0 = acc[mt][nt][0] + bv0;
            const float v1 = acc[mt][nt][1] + bv0;
            const float v2 = acc[mt][nt][2] + bv8;
            const float v3 = acc[mt][nt][3] + bv8;
            if (PHASE2) {
                const int pr = p >> 6, pc = p & 63;
                const int yy = i0 + pr;
                __half* base0 = g_O1 + ((size_t)(img * CMID + co0) * HOUT + yy) * WOUT + pc;
                __half* base8 = base0 + (size_t)8 * HOUT * WOUT;
                *reinterpret_cast<__half2*>(base0) = __floats2half2_rn(v0, v1);
                *reinterpret_cast<__half2*>(base8) = __floats2half2_rn(v2, v3);
            } else {
                const int pr = p >> 5, pc = p & 31;
                const int yy = 2 * (i0 + pr) + qr;
                const int xx = 2 * pc + qc;
                if (toX2p) {
                    // padded channel-innermost: [img][yy+1][xx+1][ch]
                    __half* d = g_X2p + ((size_t)((img * 66 + yy + 1) * 66) + xx + 1) * CMID + co0;
                    d[0]       = __float2half_rn(v0);
                    d[2 * CMID] = __float2half_rn(v1);     // xx+2
                    d[8]       = __float2half_rn(v2);      // co0+8
                    d[8 + 2 * CMID] = __float2half_rn(v3);
                } else {
                    __half* base0 = g_Y2 + ((size_t)(img * CMID + co0) * HOUT + yy) * WOUT + xx;
                    __half* base8 = base0 + (size_t)8 * HOUT * WOUT;
                    base0[0] = __float2half_rn(v0);
                    base0[2] = __float2half_rn(v1);
                    base8[0] = __float2half_rn(v2);
                    base8[2] = __float2half_rn(v3);
                }
            }
            tsum[mt][0] += v0 + v1;           tsq[mt][0] += v0 * v0 + v1 * v1;
            tsum[mt][1] += v2 + v3;           tsq[mt][1] += v2 * v2 + v3 * v3;
        }
    }

    // ---- deterministic partial reduction: lanes -> warps -> CTA slot ----
    __syncthreads();
    float2* part = reinterpret_cast<float2*>(smem_c);   // [wn][128 ch] = 4KB
#pragma unroll
    for (int mt = 0; mt < 4; ++mt)
#pragma unroll
        for (int c8 = 0; c8 < 2; ++c8) {
            float s = tsum[mt][c8], q = tsq[mt][c8];
            s += __shfl_xor_sync(0xffffffffu, s, 1);
            s += __shfl_xor_sync(0xffffffffu, s, 2);
            q += __shfl_xor_sync(0xffffffffu, q, 1);
            q += __shfl_xor_sync(0xffffffffu, q, 2);
            if ((lane & 3) == 0) {
                const int chl = wm * 64 + mt * 16 + (lane >> 2) + c8 * 8;
                part[wn * 128 + chl] = make_float2(s, q);
            }
        }
    __syncthreads();
    if (tid < 128) {
        const float2 p0 = part[tid], p1 = part[128 + tid], p2 = part[256 + tid], p3 = part[384 + tid];
        const float2 r = make_float2(p0.x + p1.x + p2.x + p3.x, p0.y + p1.y + p2.y + p3.y);
        (PHASE2 ? g_part2 : g_part1)[slot * 128 + tid] = r;
    }
}

// ---------------------------------------------------------------------------
// Kernel wrappers.  Phase 1: 1-D grid (2048) with LPT bx remap.
// Phase 2: 2-D grid, fixed 3x3.
// ---------------------------------------------------------------------------
template <int CIN_T, int WDIM, int ROWS, int MTOT, bool PHASE2>
__global__ __launch_bounds__(256, 2)
void gemm_kernel(const float* __restrict__ bias9)
{
    constexpr int NT_PER_IMG = (WDIM * WDIM) / 128;
    extern __shared__ char smem[];
    const uint32_t sb = smem_u32(smem);

    const int tid  = threadIdx.x;
    const int wid  = tid >> 5;
    const int lane = tid & 31;

    int bx, by;
    if (PHASE2) {
        bx = blockIdx.x;
        by = blockIdx.y;
    } else {
        bx = g_bxmap[blockIdx.x >> 7];      // LPT order
        by = blockIdx.x & 127;
    }
    const int m0   = bx * 128;
    const int img  = by / NT_PER_IMG;
    const int i0   = (by % NT_PER_IMG) * ROWS;
    const int slot = bx * (PHASE2 ? 512 : 128) + by;

    if (PHASE2) {
        run_gemm<3, 3, CIN_T, WDIM, ROWS, MTOT, PHASE2>(smem, sb, tid, wid, lane, m0, img, i0, slot, bias9);
    } else {
        switch ((m0 >> 8) & 3) {   // 0:(3,3) 1:(2,3) 2:(3,2) 3:(2,2)
        case 0: run_gemm<3, 3, CIN_T, WDIM, ROWS, MTOT, PHASE2>(smem, sb, tid, wid, lane, m0, img, i0, slot, bias9); break;
        case 1: run_gemm<2, 3, CIN_T, WDIM, ROWS, MTOT, PHASE2>(smem, sb, tid, wid, lane, m0, img, i0, slot, bias9); break;
        case 2: run_gemm<3, 2, CIN_T, WDIM, ROWS, MTOT, PHASE2>(smem, sb, tid, wid, lane, m0, img, i0, slot, bias9); break;
        default: run_gemm<2, 2, CIN_T, WDIM, ROWS, MTOT, PHASE2>(smem, sb, tid, wid, lane, m0, img, i0, slot, bias9); break;
        }
    }
}

// ---------------------------------------------------------------------------
// BN finalize: reduce per-CTA partials -> folded affine (a, s).
// ---------------------------------------------------------------------------
__global__ void bn_finalize12_kernel(const float* __restrict__ gA, const float* __restrict__ beA,
                                     const float* __restrict__ gB, const float* __restrict__ beB)
{
    const int which = blockIdx.y;          // 0: branch1/X2p (convs 0-3), 1: Y2 (convs 4-7)
    const int ch = blockIdx.x;
    const int mhalf = ch >> 7, chl = ch & 127;
    const int tid = threadIdx.x;

    float s = 0.0f, q = 0.0f;
    for (int i = tid; i < 512; i += 256) {
        const int cv = i >> 7, by = i & 127;
        const int bx = (which * 4 + cv) * 2 + mhalf;
        const float2 p = g_part1[(bx * 128 + by) * 128 + chl];
        s += p.x; q += p.y;
    }
    __shared__ float rs[256], rq[256];
    rs[tid] = s; rq[tid] = q;
    __syncthreads();
    for (int off = 128; off > 0; off >>= 1) {
        if (tid < off) { rs[tid] += rs[tid + off]; rq[tid] += rq[tid + off]; }
        __syncthreads();
    }
    if (tid == 0) {
        const float inv = 1.0f / 65536.0f;
        const float mean = rs[0] * inv;
        const float var  = rq[0] * inv - mean * mean;
        const float* gamma = which ? gB : gA;
        const float* beta  = which ? beB : beA;
        const float a = gamma[ch] * rsqrtf(var + 1e-5f);
        if (which) { g_a2[ch] = a; g_s2[ch] = beta[ch] - mean * a; }
        else       { g_a1[ch] = a; g_s1[ch] = beta[ch] - mean * a; }
    }
}

__global__ void bn_finalize2_kernel(const float* __restrict__ gamma, const float* __restrict__ beta)
{
    const int ch = blockIdx.x;
    const int bx = ch >> 7, chl = ch & 127;
    const int tid = threadIdx.x;

    float s = 0.0f, q = 0.0f;
    for (int by = tid; by < 512; by += 256) {
        const float2 p = g_part2[(bx * 512 + by) * 128 + chl];
        s += p.x; q += p.y;
    }
    __shared__ float rs[256], rq[256];
    rs[tid] = s; rq[tid] = q;
    __syncthreads();
    for (int off = 128; off > 0; off >>= 1) {
        if (tid < off) { rs[tid] += rs[tid + off]; rq[tid] += rq[tid + off]; }
        __syncthreads();
    }
    if (tid == 0) {
        const float inv = 1.0f / 65536.0f;
        const float mean = rs[0] * inv;
        const float var  = rq[0] * inv - mean * mean;
        const float a = gamma[ch] * rsqrtf(var + 1e-5f);
        g_a3[ch] = a;
        g_s3[ch] = beta[ch] - mean * a;
    }
}

// ---------------------------------------------------------------------------
// Final merge: out = relu( BN2(O1) + BN12(Y2) ), 8 halves per thread.
// ---------------------------------------------------------------------------
__global__ void final_kernel(float* __restrict__ out)
{
    const int idx = blockIdx.x * blockDim.x + threadIdx.x;   // over NOUT/8
    if (idx >= NOUT / 8) return;
    const int c = (idx >> 9) & (CMID - 1);                   // 512 8-groups per plane
    const float a2 = g_a2[c], s2 = g_s2[c];
    const float a3 = g_a3[c], s3 = g_s3[c];
    const uint4 ov = reinterpret_cast<const uint4*>(g_O1)[idx];
    const uint4 yv = reinterpret_cast<const uint4*>(g_Y2)[idx];
    const uint32_t ow[4] = {ov.x, ov.y, ov.z, ov.w};
    const uint32_t yw[4] = {yv.x, yv.y, yv.z, yv.w};
    float r[8];
#pragma unroll
    for (int i = 0; i < 4; ++i) {
        const float2 o2 = __half22float2(*reinterpret_cast<const __half2*>(&ow[i]));
        const float2 y2 = __half22float2(*reinterpret_cast<const __half2*>(&yw[i]));
        r[2 * i]     = fmaxf(0.0f, fmaf(o2.x, a3, s3) + fmaf(y2.x, a2, s2));
        r[2 * i + 1] = fmaxf(0.0f, fmaf(o2.y, a3, s3) + fmaf(y2.y, a2, s2));
    }
    float4* o4 = reinterpret_cast<float4*>(out) + idx * 2;
    o4[0] = make_float4(r[0], r[1], r[2], r[3]);
    o4[1] = make_float4(r[4], r[5], r[6], r[7]);
}

// ---------------------------------------------------------------------------
// Launch sequence
// ---------------------------------------------------------------------------
extern "C" void kernel_launch(void* const* d_in, const int* in_sizes, int n_in,
                              void* d_out, int out_size)
{
    const float* x   = (const float*)d_in[0];
    const float* w1  = (const float*)d_in[1];   const float* b1  = (const float*)d_in[2];
    const float* w2  = (const float*)d_in[3];   const float* b2  = (const float*)d_in[4];
    const float* w3  = (const float*)d_in[5];   const float* b3  = (const float*)d_in[6];
    const float* w4  = (const float*)d_in[7];   const float* b4  = (const float*)d_in[8];
    const float* w5  = (const float*)d_in[9];   const float* b5  = (const float*)d_in[10];
    const float* w6  = (const float*)d_in[11];  const float* b6  = (const float*)d_in[12];
    const float* w7  = (const float*)d_in[13];  const float* b7  = (const float*)d_in[14];
    const float* w8  = (const float*)d_in[15];  const float* b8  = (const float*)d_in[16];
    const float* w9  = (const float*)d_in[17];  const float* b9  = (const float*)d_in[18];
    const float* g11 = (const float*)d_in[19];  const float* be11 = (const float*)d_in[20];
    const float* g12 = (const float*)d_in[21];  const float* be12 = (const float*)d_in[22];
    const float* g2  = (const float*)d_in[23];  const float* be2  = (const float*)d_in[24];

    const int SMEM_GEMM = 3 * 32768;   // 98,304 B (3-stage pipeline, 2 CTAs/SM)
    cudaFuncSetAttribute(gemm_kernel<512, 32, 4, 2048, false>,
                         cudaFuncAttributeMaxDynamicSharedMemorySize, SMEM_GEMM);
    cudaFuncSetAttribute(gemm_kernel<256, 64, 2, 256, true>,
                         cudaFuncAttributeMaxDynamicSharedMemorySize, SMEM_GEMM);

    // Pre-passes: coalesced weight transform + input transform
    prep_weights_kernel<<<2048 + 256, 128>>>(w1, w2, w3, w4, w5, w6, w7, w8,
                                             b1, b2, b3, b4, b5, b6, b7, b8, w9);
    pad_transpose_kernel<<<BATCH * 34 * 8, 256>>>(x);

    // Phase-1 GEMM: branch-1 writes X2p directly; branch-2 writes Y2.
    gemm_kernel<512, 32, 4, 2048, false><<<2048, 256, SMEM_GEMM>>>(nullptr);

    // BN11 + BN12 finalize
    bn_finalize12_kernel<<<dim3(CMID, 2), 256>>>(g11, be11, g12, be12);

    // In-place relu(BN11) on X2p (border -> 0)
    affine_x2p_kernel<<<(BATCH * 66 * 66 * CMID / 8 + 255) / 256, 256>>>();

    // Phase-2 GEMM: conv9; fp16 epilogue -> O1.
    gemm_kernel<256, 64, 2, 256, true><<<dim3(2, 512), 256, SMEM_GEMM>>>(b9);

    // BN2 finalize
    bn_finalize2_kernel<<<CMID, 256>>>(g2, be2);

    final_kernel<<<(NOUT / 8 + 255) / 256, 256>>>((float*)d_out);
}